// round 11
// baseline (speedup 1.0000x reference)
#include <cuda_runtime.h>
#include <cuda_fp16.h>
#include <math.h>
#include <stdint.h>

#define B_  2
#define L_  16
#define C_  64
#define S_  64
#define W_  128
#define R_  32
#define H_  32
#define BL_ (B_*L_)
#define SW_ (S_*W_)
#define CR_ (C_*R_)
#define PLANES_ (BL_*C_)
#define NELEM_ (PLANES_*SW_)

// ---------------- device scratch ----------------
__device__ float    g_ctx[BL_*C_];
__device__ float    g_u_re[BL_*CR_],  g_u_im[BL_*CR_];
__device__ uint32_t g_yh[NELEM_];       // half2 (re,im) planes
__device__ uint32_t g_fh[NELEM_/2];     // half2 (o, o+1) fused planes
__device__ __half   g_Bw[9*8192];       // per-tap swizzled [o=64][k=128] fp16 weights
__device__ float    g_bias[C_*SW_];     // bias + border-tap field

// ---------------- helpers ----------------
__device__ __forceinline__ float blockReduceSum(float v, float* sbuf) {
    int lane = threadIdx.x & 31, warp = threadIdx.x >> 5;
    #pragma unroll
    for (int o = 16; o > 0; o >>= 1) v += __shfl_down_sync(0xffffffffu, v, o);
    if (lane == 0) sbuf[warp] = v;
    __syncthreads();
    int nw = blockDim.x >> 5;
    v = (threadIdx.x < nw) ? sbuf[threadIdx.x] : 0.f;
    if (warp == 0) {
        #pragma unroll
        for (int o = 16; o > 0; o >>= 1) v += __shfl_down_sync(0xffffffffu, v, o);
    }
    return v;
}
__device__ __forceinline__ uint32_t smem_u32(const void* p) {
    uint32_t a;
    asm("{ .reg .u64 t; cvta.to.shared.u64 t, %1; cvt.u32.u64 %0, t; }" : "=r"(a) : "l"(p));
    return a;
}
__device__ __forceinline__ void cp_async16(uint32_t dst, const void* src) {
    asm volatile("cp.async.cg.shared.global [%0], [%1], 16;" :: "r"(dst), "l"(src));
}
#define CP_COMMIT() asm volatile("cp.async.commit_group;" ::: "memory")
#define CP_WAIT0()  asm volatile("cp.async.wait_group 0;" ::: "memory")

// ---------------- K4+K0: u-projection MMA (blocks 0..2047) + prep (blocks 2048..2111) ----------------
#define SMEM_U_BYTES (16384 + 8192 + 32768 + 2048)
__global__ void __launch_bounds__(256) k_u_prep(const float* __restrict__ x,
        const float* __restrict__ Ur, const float* __restrict__ Ui,
        const float* __restrict__ Vr, const float* __restrict__ Vi,
        const float* __restrict__ fuse_k, const float* __restrict__ convr_k,
        const float* __restrict__ convi_k, const float* __restrict__ convr_b,
        const float* __restrict__ convi_b, const float* __restrict__ fuse_b,
        const float* __restrict__ Wr, const float* __restrict__ Wi,
        const float* __restrict__ br, const float* __restrict__ bi) {
    extern __shared__ __align__(16) char smu[];
    int tid = threadIdx.x, lane = tid & 31, warp = tid >> 5;

    if (blockIdx.x >= 2048) {
        // ======== prep branch ========
        int o = blockIdx.x - 2048;
        float* sF1 = (float*)smu;
        float* sF2 = sF1 + 64;
        float* sP  = sF2 + 64;
        float* sQ  = sP + 576;
        float* sA2 = sQ + 576;
        float* sB2 = sA2 + 576;
        float* sT  = sB2 + 576;
        float* sc0 = sT + 9;
        if (tid < 64)       sF1[tid]      = fuse_k[o*128 + tid];
        else if (tid < 128) sF2[tid - 64] = fuse_k[o*128 + tid];
        __syncthreads();
        for (int idx = tid; idx < 576; idx += 256) {
            float p = 0.f, q = 0.f;
            for (int m = 0; m < C_; m++) {
                p += sF1[m] * convr_k[m*576 + idx];
                q += sF2[m] * convi_k[m*576 + idx];
            }
            sP[idx] = p; sQ[idx] = q;
        }
        if (tid == 0) {
            float v = fuse_b[o];
            for (int m = 0; m < C_; m++) v += sF1[m]*convr_b[m] + sF2[m]*convi_b[m];
            *sc0 = v;
        }
        __syncthreads();
        for (int idx = tid; idx < 576; idx += 256) {
            int cp = idx / 9, t = idx % 9;
            float a = 0.f, bb = 0.f;
            for (int cc = 0; cc < C_; cc++) {
                float pp = sP[cc*9 + t], qq = sQ[cc*9 + t];
                float wr = Wr[cc*C_ + cp], wi = Wi[cc*C_ + cp];
                a  += pp * wr + qq * wi;
                bb += -pp * wi + qq * wr;
            }
            sA2[idx] = a; sB2[idx] = bb;
        }
        if (tid < 9) {
            float tt = 0.f;
            for (int cc = 0; cc < C_; cc++)
                tt += sP[cc*9 + tid]*br[cc] + sQ[cc*9 + tid]*bi[cc];
            sT[tid] = tt;
        }
        __syncthreads();
        for (int i = tid; i < 9*128; i += 256) {
            int tt = i >> 7, k = i & 127;
            int ci = k >> 1, reim = k & 1;
            float wv = reim ? sB2[ci*9 + tt] : sA2[ci*9 + tt];
            int chunk = k >> 3;
            g_Bw[tt*8192 + o*128 + ((chunk ^ (o & 7)) << 3) + (k & 7)] = __float2half(wv);
        }
        float T[9];
        #pragma unroll
        for (int k = 0; k < 9; k++) T[k] = sT[k];
        float c0 = *sc0;
        for (int i = tid; i < SW_; i += 256) {
            int s = i >> 7, w = i & 127;
            float b = c0;
            #pragma unroll
            for (int k = 0; k < 9; k++) {
                int ds = k/3 - 1, dw = k%3 - 1;
                if (((unsigned)(s + ds) < (unsigned)S_) && ((unsigned)(w + dw) < (unsigned)W_))
                    b += T[k];
            }
            g_bias[o*SW_ + i] = b;
        }
        return;
    }

    // ======== u-projection branch ========
    __half* sXT = (__half*)smu;
    __half* sUp = (__half*)(smu + 16384);
    float*  sV  = (float*)(smu + 16384 + 8192);
    float*  sred = (float*)(smu + 16384 + 8192 + 32768);
    int blc = blockIdx.x, c = blc & 63;

    const float* xp = x + (size_t)blc * SW_;
    float csum = 0.f;
    for (int i = tid; i < SW_; i += 256) {
        int s = i >> 7, w = i & 127;
        float xv = xp[i];
        csum += xv;
        int off = w*128 + ((((s >> 3) ^ (w & 7))) << 4) + (s & 7)*2;
        *(__half*)((char*)sXT + off) = __float2half(xv);
    }
    for (int i = tid; i < 64*64; i += 256) {
        int n = i >> 6, k = i & 63;
        int r = n >> 1;
        float v = Ur[c*2048 + k*32 + r];
        if (n & 1) v = -Ui[c*2048 + k*32 + r];
        int off = n*128 + ((((k >> 3) ^ (n & 7))) << 4) + (k & 7)*2;
        *(__half*)((char*)sUp + off) = __float2half(v);
    }
    for (int i = tid; i < W_*R_; i += 256) {
        sV[i*2]     = Vr[c*4096 + i];
        sV[i*2 + 1] = Vi[c*4096 + i];
    }
    csum = blockReduceSum(csum, sred);
    if (tid == 0) g_ctx[blc] = csum * (1.f / (float)SW_);
    __syncthreads();

    uint32_t sXu = smem_u32(sXT), sUu = smem_u32(sUp);
    int wbase = warp * 16;
    float acc[8][4];
    #pragma unroll
    for (int nt = 0; nt < 8; nt++)
        #pragma unroll
        for (int j = 0; j < 4; j++) acc[nt][j] = 0.f;

    #pragma unroll
    for (int ks = 0; ks < 4; ks++) {
        int row = wbase + (lane & 15);
        int cblk = ks*2 + (lane >> 4);
        uint32_t aaddr = sXu + row*128 + (uint32_t)((cblk ^ (row & 7)) << 4);
        uint32_t a0, a1, a2, a3;
        asm volatile("ldmatrix.sync.aligned.m8n8.x4.shared.b16 {%0,%1,%2,%3}, [%4];"
                     : "=r"(a0), "=r"(a1), "=r"(a2), "=r"(a3) : "r"(aaddr));
        #pragma unroll
        for (int np = 0; np < 4; np++) {
            int n = (np*2 + (lane >> 4))*8 + (lane & 7);
            int cb = ks*2 + ((lane >> 3) & 1);
            uint32_t baddr = sUu + n*128 + (uint32_t)((cb ^ (n & 7)) << 4);
            uint32_t b0, b1, b2, b3;
            asm volatile("ldmatrix.sync.aligned.m8n8.x4.shared.b16 {%0,%1,%2,%3}, [%4];"
                         : "=r"(b0), "=r"(b1), "=r"(b2), "=r"(b3) : "r"(baddr));
            asm volatile("mma.sync.aligned.m16n8k16.row.col.f32.f16.f16.f32 "
                         "{%0,%1,%2,%3}, {%4,%5,%6,%7}, {%8,%9}, {%0,%1,%2,%3};"
                         : "+f"(acc[np*2][0]), "+f"(acc[np*2][1]), "+f"(acc[np*2][2]), "+f"(acc[np*2][3])
                         : "r"(a0), "r"(a1), "r"(a2), "r"(a3), "r"(b0), "r"(b1));
            asm volatile("mma.sync.aligned.m16n8k16.row.col.f32.f16.f16.f32 "
                         "{%0,%1,%2,%3}, {%4,%5,%6,%7}, {%8,%9}, {%0,%1,%2,%3};"
                         : "+f"(acc[np*2+1][0]), "+f"(acc[np*2+1][1]), "+f"(acc[np*2+1][2]), "+f"(acc[np*2+1][3])
                         : "r"(a0), "r"(a1), "r"(a2), "r"(a3), "r"(b2), "r"(b3));
        }
    }
    int g = lane >> 2, tq = lane & 3;
    float pre[8], pim[8];
    #pragma unroll
    for (int nt = 0; nt < 8; nt++) { pre[nt] = 0.f; pim[nt] = 0.f; }
    {
        int w1 = wbase + g, w2 = w1 + 8;
        #pragma unroll
        for (int nt = 0; nt < 8; nt++) {
            int r = nt*4 + tq;
            float vr1 = sV[(w1*32 + r)*2], vi1 = sV[(w1*32 + r)*2 + 1];
            float vr2 = sV[(w2*32 + r)*2], vi2 = sV[(w2*32 + r)*2 + 1];
            float ar = acc[nt][0], ai = acc[nt][1];
            float br2 = acc[nt][2], bi2 = acc[nt][3];
            pre[nt] += ar*vr1 + ai*vi1 + br2*vr2 + bi2*vi2;
            pim[nt] += ai*vr1 - ar*vi1 + bi2*vr2 - br2*vi2;
        }
    }
    #pragma unroll
    for (int nt = 0; nt < 8; nt++) {
        #pragma unroll
        for (int o = 16; o >= 4; o >>= 1) {
            pre[nt] += __shfl_down_sync(0xffffffffu, pre[nt], o);
            pim[nt] += __shfl_down_sync(0xffffffffu, pim[nt], o);
        }
    }
    __syncthreads();
    if (lane < 4) {
        #pragma unroll
        for (int nt = 0; nt < 8; nt++) {
            int r = nt*4 + lane;
            sred[warp*64 + r*2]     = pre[nt];
            sred[warp*64 + r*2 + 1] = pim[nt];
        }
    }
    __syncthreads();
    if (tid < 32) {
        int r = tid;
        float ur = 0.f, ui = 0.f;
        #pragma unroll
        for (int wp = 0; wp < 8; wp++) {
            ur += sred[wp*64 + r*2];
            ui += sred[wp*64 + r*2 + 1];
        }
        g_u_re[blc*R_ + r] = ur;
        g_u_im[blc*R_ + r] = ui;
    }
}

// ---------------- K6: fused MLP+scan prologue + reconstruct MMA -> half2 planes ----------------
__global__ void __launch_bounds__(256) k_recon_mma(
        const float* __restrict__ Ur, const float* __restrict__ Ui,
        const float* __restrict__ Vr, const float* __restrict__ Vi,
        const float* __restrict__ nu_log, const float* __restrict__ th_log,
        const float* __restrict__ dnu, const float* __restrict__ dth,
        const float* __restrict__ w1, const float* __restrict__ b1,
        const float* __restrict__ w2, const float* __restrict__ b2,
        const float* __restrict__ fscale) {
    __shared__ __align__(16) __half sA[64*64];
    __shared__ __align__(16) __half sBv[256*64];
    __shared__ float sh[64];
    __shared__ float sctx[1024];
    __shared__ float shid[512];
    int tid = threadIdx.x, lane = tid & 31, warp = tid >> 5;
    int blc = blockIdx.x;
    int b = blc >> 10, l = (blc >> 6) & 15, c = blc & 63;

    // ---- prologue: MLP hidden for all 16 l of batch b ----
    for (int i = tid; i < 1024; i += 256) sctx[i] = g_ctx[b*1024 + i];
    __syncthreads();
    for (int idx = tid; idx < 512; idx += 256) {
        int ll = idx >> 5, h = idx & 31;
        float v = b1[h];
        for (int cc = 0; cc < C_; cc++) v += sctx[ll*64 + cc] * w1[cc*H_ + h];
        shid[idx] = tanhf(v);
    }
    __syncthreads();
    // ---- scan chain up to l for this (b,c), one thread per r ----
    if (tid < 32) {
        int r = tid, cr = c*32 + r;
        float fr[16], fi[16];
        float b2r = b2[2*cr], b2i = b2[2*cr + 1];
        #pragma unroll
        for (int ll = 0; ll < 16; ll++) { fr[ll] = b2r; fi[ll] = b2i; }
        for (int j = 0; j < H_; j++) {
            float wr = w2[j*(CR_*2) + 2*cr], wi = w2[j*(CR_*2) + 2*cr + 1];
            #pragma unroll
            for (int ll = 0; ll < 16; ll++) {
                float hv = shid[ll*32 + j];
                fr[ll] = fmaf(hv, wr, fr[ll]);
                fi[ll] = fmaf(hv, wi, fi[ll]);
            }
        }
        float fs = *fscale;
        float nu = expf(nu_log[cr] + dnu[cr]);
        float th = expf(th_log[cr] + dth[cr]);
        float el = expf(-nu);
        float ga = sqrtf(fmaxf(1.f - el*el, 1e-6f));
        float lr = el * cosf(th), li = el * sinf(th);
        float hr = 0.f, hi = 0.f;
        for (int ll = 0; ll <= l; ll++) {
            int idx = (b*16 + ll)*CR_ + cr;
            float mr = ga * (1.f + fs * fr[ll]);
            float mi = ga * (fs * fi[ll]);
            float ur_raw = g_u_re[idx], ui_raw = g_u_im[idx];
            float ur = mr*ur_raw - mi*ui_raw;
            float ui = mr*ui_raw + mi*ur_raw;
            float nr = lr*hr - li*hi + ur;
            float ni = lr*hi + li*hr + ui;
            hr = nr; hi = ni;
        }
        sh[r] = hr; sh[32 + r] = hi;
    }
    __syncthreads();

    // ---- A tile: g = h*U ----
    for (int i = tid; i < 2048; i += 256) {
        int s = i >> 5, r = i & 31;
        float hr = sh[r], hi = sh[32 + r];
        float ur = Ur[c*2048 + s*32 + r], ui = Ui[c*2048 + s*32 + r];
        float gr = hr*ur - hi*ui;
        float gi = hr*ui + hi*ur;
        int off = s*128 + ((((r >> 2) ^ (s & 7))) << 4) + (r & 3)*4;
        __half2 h2 = __floats2half2_rn(gr, gi);
        *(uint32_t*)((char*)sA + off) = *(uint32_t*)&h2;
    }
    for (int i = tid; i < 256*64; i += 256) {
        int n = i >> 6, k = i & 63;
        int w = n >> 1, nc = n & 1, r = k >> 1, kc = k & 1;
        float vr = Vr[c*4096 + w*32 + r], vi = Vi[c*4096 + w*32 + r];
        float v = nc ? (kc ? vr : vi) : (kc ? -vi : vr);
        int off = n*128 + ((((k >> 3) ^ (n & 7))) << 4) + (k & 7)*2;
        *(__half*)((char*)sBv + off) = __float2half(v);
    }
    __syncthreads();

    uint32_t sAu = smem_u32(sA), sBu = smem_u32(sBv);
    int mt = warp & 3, nh = warp >> 2;
    int mrow = mt * 16;
    float acc[16][4];
    #pragma unroll
    for (int nt = 0; nt < 16; nt++)
        #pragma unroll
        for (int j = 0; j < 4; j++) acc[nt][j] = 0.f;

    #pragma unroll
    for (int ks = 0; ks < 4; ks++) {
        int row = mrow + (lane & 15);
        int cblk = ks*2 + (lane >> 4);
        uint32_t aaddr = sAu + row*128 + (uint32_t)((cblk ^ (row & 7)) << 4);
        uint32_t a0, a1, a2, a3;
        asm volatile("ldmatrix.sync.aligned.m8n8.x4.shared.b16 {%0,%1,%2,%3}, [%4];"
                     : "=r"(a0), "=r"(a1), "=r"(a2), "=r"(a3) : "r"(aaddr));
        #pragma unroll
        for (int np = 0; np < 8; np++) {
            int n = (nh*16 + np*2 + (lane >> 4))*8 + (lane & 7);
            int cb = ks*2 + ((lane >> 3) & 1);
            uint32_t baddr = sBu + n*128 + (uint32_t)((cb ^ (n & 7)) << 4);
            uint32_t b0, b1, b2, b3;
            asm volatile("ldmatrix.sync.aligned.m8n8.x4.shared.b16 {%0,%1,%2,%3}, [%4];"
                         : "=r"(b0), "=r"(b1), "=r"(b2), "=r"(b3) : "r"(baddr));
            asm volatile("mma.sync.aligned.m16n8k16.row.col.f32.f16.f16.f32 "
                         "{%0,%1,%2,%3}, {%4,%5,%6,%7}, {%8,%9}, {%0,%1,%2,%3};"
                         : "+f"(acc[np*2][0]), "+f"(acc[np*2][1]), "+f"(acc[np*2][2]), "+f"(acc[np*2][3])
                         : "r"(a0), "r"(a1), "r"(a2), "r"(a3), "r"(b0), "r"(b1));
            asm volatile("mma.sync.aligned.m16n8k16.row.col.f32.f16.f16.f32 "
                         "{%0,%1,%2,%3}, {%4,%5,%6,%7}, {%8,%9}, {%0,%1,%2,%3};"
                         : "+f"(acc[np*2+1][0]), "+f"(acc[np*2+1][1]), "+f"(acc[np*2+1][2]), "+f"(acc[np*2+1][3])
                         : "r"(a0), "r"(a1), "r"(a2), "r"(a3), "r"(b2), "r"(b3));
        }
    }
    int g = lane >> 2, tq = lane & 3;
    uint32_t* py = g_yh + (size_t)blc*SW_;
    #pragma unroll
    for (int nt = 0; nt < 16; nt++) {
        int w = (nh*16 + nt)*4 + tq;
        __half2 h1 = __floats2half2_rn(acc[nt][0], acc[nt][1]);
        __half2 h2 = __floats2half2_rn(acc[nt][2], acc[nt][3]);
        py[(mrow + g)*W_ + w]     = *(uint32_t*)&h1;
        py[(mrow + g + 8)*W_ + w] = *(uint32_t*)&h2;
    }
}

// ---------------- K8: fp16 mma.sync conv-GEMM, cp.async double-buffered B ----------------
// SMEM: staged rows [6][130][64] half2 swz (199680) + 2x B tap tile (32768)
#define CONV_SMEM (199680 + 32768)
__global__ void __launch_bounds__(512) k_conv_mma() {
    extern __shared__ __align__(16) char smc[];
    int tid = threadIdx.x, lane = tid & 31, warp = tid >> 5;
    int bl = blockIdx.x >> 4, s0 = (blockIdx.x & 15) * 4;
    uint32_t sAu = smem_u32(smc);
    uint32_t sB0 = sAu + 199680;

    // stage 6 halo rows — shift-only indexing, warp-per-(ds,ci), lanes sweep pw
    const uint32_t* ybl = g_yh + (size_t)bl * (C_*SW_);
    for (int p = warp; p < 6*64; p += 16) {
        int ds = p >> 6, ci = p & 63;
        int sr = s0 + ds - 1;
        bool rok = (unsigned)sr < (unsigned)S_;
        const uint32_t* rowp = ybl + (size_t)ci*SW_ + sr*W_;
        int base = ds*33280 + ((ci & 3) << 2);
        int cihi = ci >> 2;
        for (int pw = lane; pw < 130; pw += 32) {
            int w = pw - 1;
            uint32_t v = (rok && ((unsigned)w < (unsigned)W_)) ? rowp[w] : 0u;
            int phys = base + pw*256 + ((cihi ^ (pw & 7)) << 4);
            *(uint32_t*)(smc + phys) = v;
        }
    }
    // prefetch B tap 0
    {
        uint32_t dst = sB0 + (uint32_t)(tid*16);
        const char* src = (const char*)g_Bw + tid*16;
        cp_async16(dst, src);
        cp_async16(dst + 8192, src + 8192);
        CP_COMMIT();
    }
    __syncthreads();

    float acc[2][8][4];
    #pragma unroll
    for (int mt = 0; mt < 2; mt++)
        #pragma unroll
        for (int nt = 0; nt < 8; nt++)
            #pragma unroll
            for (int j = 0; j < 4; j++) acc[mt][nt][j] = 0.f;

    int s_row = warp >> 2;
    int wbase = (warp & 3) * 32;

    #pragma unroll 1
    for (int t = 0; t < 9; t++) {
        CP_WAIT0();
        __syncthreads();
        if (t < 8) {
            uint32_t dst = sB0 + (uint32_t)(((t + 1) & 1)*16384 + tid*16);
            const char* src = (const char*)g_Bw + (t + 1)*16384 + tid*16;
            cp_async16(dst, src);
            cp_async16(dst + 8192, src + 8192);
            CP_COMMIT();
        }
        uint32_t sBt = sB0 + (uint32_t)((t & 1)*16384);
        int tx = t % 3, ds = s_row + t / 3;
        #pragma unroll 1
        for (int ks = 0; ks < 8; ks++) {
            uint32_t a0[2], a1[2], a2[2], a3[2];
            #pragma unroll
            for (int mt = 0; mt < 2; mt++) {
                int row = wbase + mt*16 + (lane & 15) + tx;
                int cblk = ks*2 + (lane >> 4);
                uint32_t aaddr = sAu + ds*33280 + row*256 + (uint32_t)((cblk ^ (row & 7)) << 4);
                asm volatile("ldmatrix.sync.aligned.m8n8.x4.shared.b16 {%0,%1,%2,%3}, [%4];"
                             : "=r"(a0[mt]), "=r"(a1[mt]), "=r"(a2[mt]), "=r"(a3[mt]) : "r"(aaddr));
            }
            #pragma unroll
            for (int np = 0; np < 4; np++) {
                int n = (np*2 + (lane >> 4))*8 + (lane & 7);
                int cb = ks*2 + ((lane >> 3) & 1);
                uint32_t baddr = sBt + n*256 + (uint32_t)((cb ^ (n & 7)) << 4);
                uint32_t b0, b1, b2, b3;
                asm volatile("ldmatrix.sync.aligned.m8n8.x4.shared.b16 {%0,%1,%2,%3}, [%4];"
                             : "=r"(b0), "=r"(b1), "=r"(b2), "=r"(b3) : "r"(baddr));
                #pragma unroll
                for (int mt = 0; mt < 2; mt++) {
                    asm volatile("mma.sync.aligned.m16n8k16.row.col.f32.f16.f16.f32 "
                                 "{%0,%1,%2,%3}, {%4,%5,%6,%7}, {%8,%9}, {%0,%1,%2,%3};"
                                 : "+f"(acc[mt][np*2][0]), "+f"(acc[mt][np*2][1]),
                                   "+f"(acc[mt][np*2][2]), "+f"(acc[mt][np*2][3])
                                 : "r"(a0[mt]), "r"(a1[mt]), "r"(a2[mt]), "r"(a3[mt]),
                                   "r"(b0), "r"(b1));
                    asm volatile("mma.sync.aligned.m16n8k16.row.col.f32.f16.f16.f32 "
                                 "{%0,%1,%2,%3}, {%4,%5,%6,%7}, {%8,%9}, {%0,%1,%2,%3};"
                                 : "+f"(acc[mt][np*2+1][0]), "+f"(acc[mt][np*2+1][1]),
                                   "+f"(acc[mt][np*2+1][2]), "+f"(acc[mt][np*2+1][3])
                                 : "r"(a0[mt]), "r"(a1[mt]), "r"(a2[mt]), "r"(a3[mt]),
                                   "r"(b2), "r"(b3));
                }
            }
        }
    }
    int g = lane >> 2, tq = lane & 3;
    #pragma unroll
    for (int mt = 0; mt < 2; mt++) {
        uint32_t* ob = g_fh + (size_t)bl * (32*SW_) + (s0 + s_row)*W_ + wbase + mt*16 + g;
        #pragma unroll
        for (int nt = 0; nt < 8; nt++) {
            int pi = nt*4 + tq;
            __half2 hA = __floats2half2_rn(acc[mt][nt][0], acc[mt][nt][1]);
            __half2 hB = __floats2half2_rn(acc[mt][nt][2], acc[mt][nt][3]);
            ob[(size_t)pi*SW_]     = *(uint32_t*)&hA;
            ob[(size_t)pi*SW_ + 8] = *(uint32_t*)&hB;
        }
    }
}

// ---------------- K9: LayerNorm over o-pairs (+ bias) + residual ----------------
__global__ void __launch_bounds__(512) k_ln(const float* __restrict__ x,
                     const float* __restrict__ lng,
                     const float* __restrict__ lnb, float* __restrict__ out) {
    __shared__ float sbuf1[16], sbuf2[16];
    __shared__ float s_mu0, s_r0, s_mu1, s_r1;
    int blc2 = blockIdx.x, tid = threadIdx.x;
    int bl = blc2 >> 5, op = blc2 & 31;
    int o0 = op * 2;
    const uint32_t* fp = g_fh + (size_t)blc2 * SW_;
    const float* bp0 = g_bias + (size_t)o0 * SW_;
    const float* bp1 = g_bias + (size_t)(o0 + 1) * SW_;
    float v0[16], v1[16];
    float sum0 = 0.f, sq0 = 0.f, sum1 = 0.f, sq1 = 0.f;
    #pragma unroll
    for (int k = 0; k < 16; k++) {
        int i = tid + 512*k;
        uint32_t u = fp[i];
        __half2 h = *(__half2*)&u;
        float2 f = __half22float2(h);
        float t0 = f.x + bp0[i];
        float t1 = f.y + bp1[i];
        v0[k] = t0; v1[k] = t1;
        sum0 += t0; sq0 += t0*t0;
        sum1 += t1; sq1 += t1*t1;
    }
    float ts0 = blockReduceSum(sum0, sbuf1);
    __syncthreads();
    float tq0 = blockReduceSum(sq0, sbuf2);
    __syncthreads();
    float ts1 = blockReduceSum(sum1, sbuf1);
    __syncthreads();
    float tq1 = blockReduceSum(sq1, sbuf2);
    if (tid == 0) {
        float mu0 = ts0 * (1.f / (float)SW_);
        float var0 = tq0 * (1.f / (float)SW_) - mu0*mu0;
        s_mu0 = mu0; s_r0 = rsqrtf(var0 + 1e-5f);
        float mu1 = ts1 * (1.f / (float)SW_);
        float var1 = tq1 * (1.f / (float)SW_) - mu1*mu1;
        s_mu1 = mu1; s_r1 = rsqrtf(var1 + 1e-5f);
    }
    __syncthreads();
    float mu0 = s_mu0, r0 = s_r0, mu1 = s_mu1, r1 = s_r1;
    const float* xp0 = x + ((size_t)bl*C_ + o0)*SW_;
    const float* xp1 = xp0 + SW_;
    float* op0 = out + ((size_t)bl*C_ + o0)*SW_;
    float* op1 = op0 + SW_;
    #pragma unroll
    for (int k = 0; k < 16; k++) {
        int i = tid + 512*k;
        float gg = lng[i], bb = lnb[i];
        op0[i] = (v0[k] - mu0) * r0 * gg + bb + xp0[i];
        op1[i] = (v1[k] - mu1) * r1 * gg + bb + xp1[i];
    }
}

// ---------------- launch ----------------
extern "C" void kernel_launch(void* const* d_in, const int* in_sizes, int n_in,
                              void* d_out, int out_size) {
    const float* x         = (const float*)d_in[0];
    const float* nu_log    = (const float*)d_in[1];
    const float* theta_log = (const float*)d_in[2];
    const float* disp_nu   = (const float*)d_in[3];
    const float* disp_th   = (const float*)d_in[4];
    const float* mlp_w1    = (const float*)d_in[5];
    const float* mlp_b1    = (const float*)d_in[6];
    const float* mlp_w2    = (const float*)d_in[7];
    const float* mlp_b2    = (const float*)d_in[8];
    const float* fscale    = (const float*)d_in[9];
    const float* U_row_r   = (const float*)d_in[10];
    const float* U_row_i   = (const float*)d_in[11];
    const float* V_col_r   = (const float*)d_in[12];
    const float* V_col_i   = (const float*)d_in[13];
    const float* proj_W_r  = (const float*)d_in[14];
    const float* proj_W_i  = (const float*)d_in[15];
    const float* proj_b_r  = (const float*)d_in[16];
    const float* proj_b_i  = (const float*)d_in[17];
    const float* convr_k   = (const float*)d_in[18];
    const float* convr_b   = (const float*)d_in[19];
    const float* convi_k   = (const float*)d_in[20];
    const float* convi_b   = (const float*)d_in[21];
    const float* fuse_k    = (const float*)d_in[22];
    const float* fuse_b    = (const float*)d_in[23];
    const float* ln_g      = (const float*)d_in[24];
    const float* ln_b      = (const float*)d_in[25];
    float* out = (float*)d_out;

    cudaFuncSetAttribute(k_u_prep,   cudaFuncAttributeMaxDynamicSharedMemorySize, SMEM_U_BYTES);
    cudaFuncSetAttribute(k_conv_mma, cudaFuncAttributeMaxDynamicSharedMemorySize, CONV_SMEM);

    k_u_prep<<<2112, 256, SMEM_U_BYTES>>>(x, U_row_r, U_row_i, V_col_r, V_col_i,
                                          fuse_k, convr_k, convi_k, convr_b, convi_b, fuse_b,
                                          proj_W_r, proj_W_i, proj_b_r, proj_b_i);
    k_recon_mma<<<PLANES_, 256>>>(U_row_r, U_row_i, V_col_r, V_col_i,
                                  nu_log, theta_log, disp_nu, disp_th,
                                  mlp_w1, mlp_b1, mlp_w2, mlp_b2, fscale);
    k_conv_mma<<<512, 512, CONV_SMEM>>>();
    k_ln<<<1024, 512>>>(x, ln_g, ln_b, out);
}

// round 12
// speedup vs baseline: 1.1049x; 1.1049x over previous
#include <cuda_runtime.h>
#include <cuda_fp16.h>
#include <math.h>
#include <stdint.h>

#define B_  2
#define L_  16
#define C_  64
#define S_  64
#define W_  128
#define R_  32
#define H_  32
#define BL_ (B_*L_)
#define SW_ (S_*W_)
#define CR_ (C_*R_)
#define PLANES_ (BL_*C_)
#define NELEM_ (PLANES_*SW_)

// ---------------- device scratch ----------------
__device__ float    g_ctx[BL_*C_];
__device__ float    g_u_re[BL_*CR_],  g_u_im[BL_*CR_];
__device__ float    g_h_re[BL_*CR_],  g_h_im[BL_*CR_];
__device__ uint32_t g_yh[NELEM_];       // half2 (re,im) planes
__device__ uint32_t g_fh[NELEM_/2];     // half2 (o, o+1) fused planes
__device__ __half   g_Bw[9*8192];       // per-tap swizzled [o=64][k=128] fp16 weights
__device__ float    g_bias[C_*SW_];     // bias + border-tap field

// ---------------- helpers ----------------
__device__ __forceinline__ float blockReduceSum(float v, float* sbuf) {
    int lane = threadIdx.x & 31, warp = threadIdx.x >> 5;
    #pragma unroll
    for (int o = 16; o > 0; o >>= 1) v += __shfl_down_sync(0xffffffffu, v, o);
    if (lane == 0) sbuf[warp] = v;
    __syncthreads();
    int nw = blockDim.x >> 5;
    v = (threadIdx.x < nw) ? sbuf[threadIdx.x] : 0.f;
    if (warp == 0) {
        #pragma unroll
        for (int o = 16; o > 0; o >>= 1) v += __shfl_down_sync(0xffffffffu, v, o);
    }
    return v;
}
__device__ __forceinline__ uint32_t smem_u32(const void* p) {
    uint32_t a;
    asm("{ .reg .u64 t; cvta.to.shared.u64 t, %1; cvt.u32.u64 %0, t; }" : "=r"(a) : "l"(p));
    return a;
}
__device__ __forceinline__ void cp_async16(uint32_t dst, const void* src) {
    asm volatile("cp.async.cg.shared.global [%0], [%1], 16;" :: "r"(dst), "l"(src));
}
#define CP_COMMIT() asm volatile("cp.async.commit_group;" ::: "memory")
#define CP_WAIT0()  asm volatile("cp.async.wait_group 0;" ::: "memory")

// ---------------- K4+K0: u-projection MMA (blocks 0..2047) + prep (blocks 2048..2111) ----------------
#define SMEM_U_BYTES (16384 + 8192 + 32768 + 2048)
__global__ void __launch_bounds__(256) k_u_prep(const float* __restrict__ x,
        const float* __restrict__ Ur, const float* __restrict__ Ui,
        const float* __restrict__ Vr, const float* __restrict__ Vi,
        const float* __restrict__ fuse_k, const float* __restrict__ convr_k,
        const float* __restrict__ convi_k, const float* __restrict__ convr_b,
        const float* __restrict__ convi_b, const float* __restrict__ fuse_b,
        const float* __restrict__ Wr, const float* __restrict__ Wi,
        const float* __restrict__ br, const float* __restrict__ bi) {
    extern __shared__ __align__(16) char smu[];
    int tid = threadIdx.x, lane = tid & 31, warp = tid >> 5;

    if (blockIdx.x >= 2048) {
        // ======== prep branch ========
        int o = blockIdx.x - 2048;
        float* sF1 = (float*)smu;
        float* sF2 = sF1 + 64;
        float* sP  = sF2 + 64;
        float* sQ  = sP + 576;
        float* sA2 = sQ + 576;
        float* sB2 = sA2 + 576;
        float* sT  = sB2 + 576;
        float* sc0 = sT + 9;
        if (tid < 64)       sF1[tid]      = fuse_k[o*128 + tid];
        else if (tid < 128) sF2[tid - 64] = fuse_k[o*128 + tid];
        __syncthreads();
        for (int idx = tid; idx < 576; idx += 256) {
            float p = 0.f, q = 0.f;
            for (int m = 0; m < C_; m++) {
                p += sF1[m] * convr_k[m*576 + idx];
                q += sF2[m] * convi_k[m*576 + idx];
            }
            sP[idx] = p; sQ[idx] = q;
        }
        if (tid == 0) {
            float v = fuse_b[o];
            for (int m = 0; m < C_; m++) v += sF1[m]*convr_b[m] + sF2[m]*convi_b[m];
            *sc0 = v;
        }
        __syncthreads();
        for (int idx = tid; idx < 576; idx += 256) {
            int cp = idx / 9, t = idx % 9;
            float a = 0.f, bb = 0.f;
            for (int cc = 0; cc < C_; cc++) {
                float pp = sP[cc*9 + t], qq = sQ[cc*9 + t];
                float wr = Wr[cc*C_ + cp], wi = Wi[cc*C_ + cp];
                a  += pp * wr + qq * wi;
                bb += -pp * wi + qq * wr;
            }
            sA2[idx] = a; sB2[idx] = bb;
        }
        if (tid < 9) {
            float tt = 0.f;
            for (int cc = 0; cc < C_; cc++)
                tt += sP[cc*9 + tid]*br[cc] + sQ[cc*9 + tid]*bi[cc];
            sT[tid] = tt;
        }
        __syncthreads();
        for (int i = tid; i < 9*128; i += 256) {
            int tt = i >> 7, k = i & 127;
            int ci = k >> 1, reim = k & 1;
            float wv = reim ? sB2[ci*9 + tt] : sA2[ci*9 + tt];
            int chunk = k >> 3;
            g_Bw[tt*8192 + o*128 + ((chunk ^ (o & 7)) << 3) + (k & 7)] = __float2half(wv);
        }
        float T[9];
        #pragma unroll
        for (int k = 0; k < 9; k++) T[k] = sT[k];
        float c0 = *sc0;
        for (int i = tid; i < SW_; i += 256) {
            int s = i >> 7, w = i & 127;
            float b = c0;
            #pragma unroll
            for (int k = 0; k < 9; k++) {
                int ds = k/3 - 1, dw = k%3 - 1;
                if (((unsigned)(s + ds) < (unsigned)S_) && ((unsigned)(w + dw) < (unsigned)W_))
                    b += T[k];
            }
            g_bias[o*SW_ + i] = b;
        }
        return;
    }

    // ======== u-projection branch ========
    __half* sXT = (__half*)smu;
    __half* sUp = (__half*)(smu + 16384);
    float*  sV  = (float*)(smu + 16384 + 8192);
    float*  sred = (float*)(smu + 16384 + 8192 + 32768);
    int blc = blockIdx.x, c = blc & 63;

    const float* xp = x + (size_t)blc * SW_;
    float csum = 0.f;
    for (int i = tid; i < SW_; i += 256) {
        int s = i >> 7, w = i & 127;
        float xv = xp[i];
        csum += xv;
        int off = w*128 + ((((s >> 3) ^ (w & 7))) << 4) + (s & 7)*2;
        *(__half*)((char*)sXT + off) = __float2half(xv);
    }
    for (int i = tid; i < 64*64; i += 256) {
        int n = i >> 6, k = i & 63;
        int r = n >> 1;
        float v = Ur[c*2048 + k*32 + r];
        if (n & 1) v = -Ui[c*2048 + k*32 + r];
        int off = n*128 + ((((k >> 3) ^ (n & 7))) << 4) + (k & 7)*2;
        *(__half*)((char*)sUp + off) = __float2half(v);
    }
    for (int i = tid; i < W_*R_; i += 256) {
        sV[i*2]     = Vr[c*4096 + i];
        sV[i*2 + 1] = Vi[c*4096 + i];
    }
    csum = blockReduceSum(csum, sred);
    if (tid == 0) g_ctx[blc] = csum * (1.f / (float)SW_);
    __syncthreads();

    uint32_t sXu = smem_u32(sXT), sUu = smem_u32(sUp);
    int wbase = warp * 16;
    float acc[8][4];
    #pragma unroll
    for (int nt = 0; nt < 8; nt++)
        #pragma unroll
        for (int j = 0; j < 4; j++) acc[nt][j] = 0.f;

    #pragma unroll
    for (int ks = 0; ks < 4; ks++) {
        int row = wbase + (lane & 15);
        int cblk = ks*2 + (lane >> 4);
        uint32_t aaddr = sXu + row*128 + (uint32_t)((cblk ^ (row & 7)) << 4);
        uint32_t a0, a1, a2, a3;
        asm volatile("ldmatrix.sync.aligned.m8n8.x4.shared.b16 {%0,%1,%2,%3}, [%4];"
                     : "=r"(a0), "=r"(a1), "=r"(a2), "=r"(a3) : "r"(aaddr));
        #pragma unroll
        for (int np = 0; np < 4; np++) {
            int n = (np*2 + (lane >> 4))*8 + (lane & 7);
            int cb = ks*2 + ((lane >> 3) & 1);
            uint32_t baddr = sUu + n*128 + (uint32_t)((cb ^ (n & 7)) << 4);
            uint32_t b0, b1, b2, b3;
            asm volatile("ldmatrix.sync.aligned.m8n8.x4.shared.b16 {%0,%1,%2,%3}, [%4];"
                         : "=r"(b0), "=r"(b1), "=r"(b2), "=r"(b3) : "r"(baddr));
            asm volatile("mma.sync.aligned.m16n8k16.row.col.f32.f16.f16.f32 "
                         "{%0,%1,%2,%3}, {%4,%5,%6,%7}, {%8,%9}, {%0,%1,%2,%3};"
                         : "+f"(acc[np*2][0]), "+f"(acc[np*2][1]), "+f"(acc[np*2][2]), "+f"(acc[np*2][3])
                         : "r"(a0), "r"(a1), "r"(a2), "r"(a3), "r"(b0), "r"(b1));
            asm volatile("mma.sync.aligned.m16n8k16.row.col.f32.f16.f16.f32 "
                         "{%0,%1,%2,%3}, {%4,%5,%6,%7}, {%8,%9}, {%0,%1,%2,%3};"
                         : "+f"(acc[np*2+1][0]), "+f"(acc[np*2+1][1]), "+f"(acc[np*2+1][2]), "+f"(acc[np*2+1][3])
                         : "r"(a0), "r"(a1), "r"(a2), "r"(a3), "r"(b2), "r"(b3));
        }
    }
    int g = lane >> 2, tq = lane & 3;
    float pre[8], pim[8];
    #pragma unroll
    for (int nt = 0; nt < 8; nt++) { pre[nt] = 0.f; pim[nt] = 0.f; }
    {
        int w1 = wbase + g, w2 = w1 + 8;
        #pragma unroll
        for (int nt = 0; nt < 8; nt++) {
            int r = nt*4 + tq;
            float vr1 = sV[(w1*32 + r)*2], vi1 = sV[(w1*32 + r)*2 + 1];
            float vr2 = sV[(w2*32 + r)*2], vi2 = sV[(w2*32 + r)*2 + 1];
            float ar = acc[nt][0], ai = acc[nt][1];
            float br2 = acc[nt][2], bi2 = acc[nt][3];
            pre[nt] += ar*vr1 + ai*vi1 + br2*vr2 + bi2*vi2;
            pim[nt] += ai*vr1 - ar*vi1 + bi2*vr2 - br2*vi2;
        }
    }
    #pragma unroll
    for (int nt = 0; nt < 8; nt++) {
        #pragma unroll
        for (int o = 16; o >= 4; o >>= 1) {
            pre[nt] += __shfl_down_sync(0xffffffffu, pre[nt], o);
            pim[nt] += __shfl_down_sync(0xffffffffu, pim[nt], o);
        }
    }
    __syncthreads();
    if (lane < 4) {
        #pragma unroll
        for (int nt = 0; nt < 8; nt++) {
            int r = nt*4 + lane;
            sred[warp*64 + r*2]     = pre[nt];
            sred[warp*64 + r*2 + 1] = pim[nt];
        }
    }
    __syncthreads();
    if (tid < 32) {
        int r = tid;
        float ur = 0.f, ui = 0.f;
        #pragma unroll
        for (int wp = 0; wp < 8; wp++) {
            ur += sred[wp*64 + r*2];
            ui += sred[wp*64 + r*2 + 1];
        }
        g_u_re[blc*R_ + r] = ur;
        g_u_im[blc*R_ + r] = ui;
    }
}

// ---------------- K5: fused MLP + modulation + scan (standalone, R10 structure) ----------------
__global__ void __launch_bounds__(256) k_scan(
        const float* __restrict__ nu_log, const float* __restrict__ th_log,
        const float* __restrict__ dnu, const float* __restrict__ dth,
        const float* __restrict__ w1, const float* __restrict__ b1,
        const float* __restrict__ w2, const float* __restrict__ b2,
        const float* __restrict__ fscale) {
    __shared__ float sctx[16*64];
    __shared__ float shid[16*32];
    int tid = threadIdx.x;
    int b = blockIdx.x >> 3, chunk = blockIdx.x & 7;
    int cr = chunk*256 + tid;

    for (int i = tid; i < 16*64; i += 256)
        sctx[i] = g_ctx[b*16*64 + i];
    __syncthreads();
    for (int idx = tid; idx < 512; idx += 256) {
        int l = idx >> 5, h = idx & 31;
        float v = b1[h];
        for (int cc = 0; cc < C_; cc++) v += sctx[l*64 + cc] * w1[cc*H_ + h];
        shid[l*32 + h] = tanhf(v);
    }
    __syncthreads();

    float fr[16], fi[16];
    float b2r = b2[2*cr], b2i = b2[2*cr + 1];
    #pragma unroll
    for (int l = 0; l < 16; l++) { fr[l] = b2r; fi[l] = b2i; }
    for (int j = 0; j < H_; j++) {
        float wr = w2[j*(CR_*2) + 2*cr];
        float wi = w2[j*(CR_*2) + 2*cr + 1];
        #pragma unroll
        for (int l = 0; l < 16; l++) {
            float hv = shid[l*32 + j];
            fr[l] = fmaf(hv, wr, fr[l]);
            fi[l] = fmaf(hv, wi, fi[l]);
        }
    }
    float fs = *fscale;
    float nu = expf(nu_log[cr] + dnu[cr]);
    float th = expf(th_log[cr] + dth[cr]);
    float el = expf(-nu);
    float ga = sqrtf(fmaxf(1.f - el*el, 1e-6f));
    float lr = el * cosf(th), li = el * sinf(th);
    float hr = 0.f, hi = 0.f;
    #pragma unroll
    for (int l = 0; l < L_; l++) {
        int idx = (b*L_ + l)*CR_ + cr;
        float mr = ga * (1.f + fs * fr[l]);
        float mi = ga * (fs * fi[l]);
        float ur_raw = g_u_re[idx], ui_raw = g_u_im[idx];
        float ur = mr*ur_raw - mi*ui_raw;
        float ui = mr*ui_raw + mi*ur_raw;
        float nr = lr*hr - li*hi + ur;
        float ni = lr*hi + li*hr + ui;
        hr = nr; hi = ni;
        g_h_re[idx] = hr;
        g_h_im[idx] = hi;
    }
}

// ---------------- K6: reconstruct via mma.sync -> half2 planes (R10 structure) ----------------
__global__ void __launch_bounds__(256) k_recon_mma(
        const float* __restrict__ Ur, const float* __restrict__ Ui,
        const float* __restrict__ Vr, const float* __restrict__ Vi) {
    __shared__ __align__(16) __half sA[64*64];
    __shared__ __align__(16) __half sBv[256*64];
    __shared__ float sh[64];
    int tid = threadIdx.x, lane = tid & 31, warp = tid >> 5;
    int blc = blockIdx.x, c = blc & 63;
    if (tid < 64) sh[tid] = (tid < 32) ? g_h_re[blc*R_ + tid] : g_h_im[blc*R_ + tid - 32];
    __syncthreads();
    for (int i = tid; i < 2048; i += 256) {
        int s = i >> 5, r = i & 31;
        float hr = sh[r], hi = sh[32 + r];
        float ur = Ur[c*2048 + s*32 + r], ui = Ui[c*2048 + s*32 + r];
        float gr = hr*ur - hi*ui;
        float gi = hr*ui + hi*ur;
        int off = s*128 + ((((r >> 2) ^ (s & 7))) << 4) + (r & 3)*4;
        __half2 h2 = __floats2half2_rn(gr, gi);
        *(uint32_t*)((char*)sA + off) = *(uint32_t*)&h2;
    }
    for (int i = tid; i < 256*64; i += 256) {
        int n = i >> 6, k = i & 63;
        int w = n >> 1, nc = n & 1, r = k >> 1, kc = k & 1;
        float vr = Vr[c*4096 + w*32 + r], vi = Vi[c*4096 + w*32 + r];
        float v = nc ? (kc ? vr : vi) : (kc ? -vi : vr);
        int off = n*128 + ((((k >> 3) ^ (n & 7))) << 4) + (k & 7)*2;
        *(__half*)((char*)sBv + off) = __float2half(v);
    }
    __syncthreads();

    uint32_t sAu = smem_u32(sA), sBu = smem_u32(sBv);
    int mt = warp & 3, nh = warp >> 2;
    int mrow = mt * 16;
    float acc[16][4];
    #pragma unroll
    for (int nt = 0; nt < 16; nt++)
        #pragma unroll
        for (int j = 0; j < 4; j++) acc[nt][j] = 0.f;

    #pragma unroll
    for (int ks = 0; ks < 4; ks++) {
        int row = mrow + (lane & 15);
        int cblk = ks*2 + (lane >> 4);
        uint32_t aaddr = sAu + row*128 + (uint32_t)((cblk ^ (row & 7)) << 4);
        uint32_t a0, a1, a2, a3;
        asm volatile("ldmatrix.sync.aligned.m8n8.x4.shared.b16 {%0,%1,%2,%3}, [%4];"
                     : "=r"(a0), "=r"(a1), "=r"(a2), "=r"(a3) : "r"(aaddr));
        #pragma unroll
        for (int np = 0; np < 8; np++) {
            int n = (nh*16 + np*2 + (lane >> 4))*8 + (lane & 7);
            int cb = ks*2 + ((lane >> 3) & 1);
            uint32_t baddr = sBu + n*128 + (uint32_t)((cb ^ (n & 7)) << 4);
            uint32_t b0, b1, b2, b3;
            asm volatile("ldmatrix.sync.aligned.m8n8.x4.shared.b16 {%0,%1,%2,%3}, [%4];"
                         : "=r"(b0), "=r"(b1), "=r"(b2), "=r"(b3) : "r"(baddr));
            asm volatile("mma.sync.aligned.m16n8k16.row.col.f32.f16.f16.f32 "
                         "{%0,%1,%2,%3}, {%4,%5,%6,%7}, {%8,%9}, {%0,%1,%2,%3};"
                         : "+f"(acc[np*2][0]), "+f"(acc[np*2][1]), "+f"(acc[np*2][2]), "+f"(acc[np*2][3])
                         : "r"(a0), "r"(a1), "r"(a2), "r"(a3), "r"(b0), "r"(b1));
            asm volatile("mma.sync.aligned.m16n8k16.row.col.f32.f16.f16.f32 "
                         "{%0,%1,%2,%3}, {%4,%5,%6,%7}, {%8,%9}, {%0,%1,%2,%3};"
                         : "+f"(acc[np*2+1][0]), "+f"(acc[np*2+1][1]), "+f"(acc[np*2+1][2]), "+f"(acc[np*2+1][3])
                         : "r"(a0), "r"(a1), "r"(a2), "r"(a3), "r"(b2), "r"(b3));
        }
    }
    int g = lane >> 2, tq = lane & 3;
    uint32_t* py = g_yh + (size_t)blc*SW_;
    #pragma unroll
    for (int nt = 0; nt < 16; nt++) {
        int w = (nh*16 + nt)*4 + tq;
        __half2 h1 = __floats2half2_rn(acc[nt][0], acc[nt][1]);
        __half2 h2 = __floats2half2_rn(acc[nt][2], acc[nt][3]);
        py[(mrow + g)*W_ + w]     = *(uint32_t*)&h1;
        py[(mrow + g + 8)*W_ + w] = *(uint32_t*)&h2;
    }
}

// ---------------- K8: fp16 mma.sync conv-GEMM, cp.async double-buffered B ----------------
#define CONV_SMEM (199680 + 32768)
__global__ void __launch_bounds__(512) k_conv_mma() {
    extern __shared__ __align__(16) char smc[];
    int tid = threadIdx.x, lane = tid & 31, warp = tid >> 5;
    int bl = blockIdx.x >> 4, s0 = (blockIdx.x & 15) * 4;
    uint32_t sAu = smem_u32(smc);
    uint32_t sB0 = sAu + 199680;

    // stage 6 halo rows — shift-only indexing
    const uint32_t* ybl = g_yh + (size_t)bl * (C_*SW_);
    for (int p = warp; p < 6*64; p += 16) {
        int ds = p >> 6, ci = p & 63;
        int sr = s0 + ds - 1;
        bool rok = (unsigned)sr < (unsigned)S_;
        const uint32_t* rowp = ybl + (size_t)ci*SW_ + sr*W_;
        int base = ds*33280 + ((ci & 3) << 2);
        int cihi = ci >> 2;
        for (int pw = lane; pw < 130; pw += 32) {
            int w = pw - 1;
            uint32_t v = (rok && ((unsigned)w < (unsigned)W_)) ? rowp[w] : 0u;
            int phys = base + pw*256 + ((cihi ^ (pw & 7)) << 4);
            *(uint32_t*)(smc + phys) = v;
        }
    }
    // prefetch B tap 0
    {
        uint32_t dst = sB0 + (uint32_t)(tid*16);
        const char* src = (const char*)g_Bw + tid*16;
        cp_async16(dst, src);
        cp_async16(dst + 8192, src + 8192);
        CP_COMMIT();
    }
    __syncthreads();

    float acc[2][8][4];
    #pragma unroll
    for (int mt = 0; mt < 2; mt++)
        #pragma unroll
        for (int nt = 0; nt < 8; nt++)
            #pragma unroll
            for (int j = 0; j < 4; j++) acc[mt][nt][j] = 0.f;

    int s_row = warp >> 2;
    int wbase = (warp & 3) * 32;

    #pragma unroll 1
    for (int t = 0; t < 9; t++) {
        CP_WAIT0();
        __syncthreads();
        if (t < 8) {
            uint32_t dst = sB0 + (uint32_t)(((t + 1) & 1)*16384 + tid*16);
            const char* src = (const char*)g_Bw + (t + 1)*16384 + tid*16;
            cp_async16(dst, src);
            cp_async16(dst + 8192, src + 8192);
            CP_COMMIT();
        }
        uint32_t sBt = sB0 + (uint32_t)((t & 1)*16384);
        int tx = t % 3, ds = s_row + t / 3;
        #pragma unroll 1
        for (int ks = 0; ks < 8; ks++) {
            uint32_t a0[2], a1[2], a2[2], a3[2];
            #pragma unroll
            for (int mt = 0; mt < 2; mt++) {
                int row = wbase + mt*16 + (lane & 15) + tx;
                int cblk = ks*2 + (lane >> 4);
                uint32_t aaddr = sAu + ds*33280 + row*256 + (uint32_t)((cblk ^ (row & 7)) << 4);
                asm volatile("ldmatrix.sync.aligned.m8n8.x4.shared.b16 {%0,%1,%2,%3}, [%4];"
                             : "=r"(a0[mt]), "=r"(a1[mt]), "=r"(a2[mt]), "=r"(a3[mt]) : "r"(aaddr));
            }
            #pragma unroll
            for (int np = 0; np < 4; np++) {
                int n = (np*2 + (lane >> 4))*8 + (lane & 7);
                int cb = ks*2 + ((lane >> 3) & 1);
                uint32_t baddr = sBt + n*256 + (uint32_t)((cb ^ (n & 7)) << 4);
                uint32_t b0, b1, b2, b3;
                asm volatile("ldmatrix.sync.aligned.m8n8.x4.shared.b16 {%0,%1,%2,%3}, [%4];"
                             : "=r"(b0), "=r"(b1), "=r"(b2), "=r"(b3) : "r"(baddr));
                #pragma unroll
                for (int mt = 0; mt < 2; mt++) {
                    asm volatile("mma.sync.aligned.m16n8k16.row.col.f32.f16.f16.f32 "
                                 "{%0,%1,%2,%3}, {%4,%5,%6,%7}, {%8,%9}, {%0,%1,%2,%3};"
                                 : "+f"(acc[mt][np*2][0]), "+f"(acc[mt][np*2][1]),
                                   "+f"(acc[mt][np*2][2]), "+f"(acc[mt][np*2][3])
                                 : "r"(a0[mt]), "r"(a1[mt]), "r"(a2[mt]), "r"(a3[mt]),
                                   "r"(b0), "r"(b1));
                    asm volatile("mma.sync.aligned.m16n8k16.row.col.f32.f16.f16.f32 "
                                 "{%0,%1,%2,%3}, {%4,%5,%6,%7}, {%8,%9}, {%0,%1,%2,%3};"
                                 : "+f"(acc[mt][np*2+1][0]), "+f"(acc[mt][np*2+1][1]),
                                   "+f"(acc[mt][np*2+1][2]), "+f"(acc[mt][np*2+1][3])
                                 : "r"(a0[mt]), "r"(a1[mt]), "r"(a2[mt]), "r"(a3[mt]),
                                   "r"(b2), "r"(b3));
                }
            }
        }
    }
    int g = lane >> 2, tq = lane & 3;
    #pragma unroll
    for (int mt = 0; mt < 2; mt++) {
        uint32_t* ob = g_fh + (size_t)bl * (32*SW_) + (s0 + s_row)*W_ + wbase + mt*16 + g;
        #pragma unroll
        for (int nt = 0; nt < 8; nt++) {
            int pi = nt*4 + tq;
            __half2 hA = __floats2half2_rn(acc[mt][nt][0], acc[mt][nt][1]);
            __half2 hB = __floats2half2_rn(acc[mt][nt][2], acc[mt][nt][3]);
            ob[(size_t)pi*SW_]     = *(uint32_t*)&hA;
            ob[(size_t)pi*SW_ + 8] = *(uint32_t*)&hB;
        }
    }
}

// ---------------- K9: LayerNorm over o-pairs (+ bias) + residual ----------------
__global__ void __launch_bounds__(512) k_ln(const float* __restrict__ x,
                     const float* __restrict__ lng,
                     const float* __restrict__ lnb, float* __restrict__ out) {
    __shared__ float sbuf1[16], sbuf2[16];
    __shared__ float s_mu0, s_r0, s_mu1, s_r1;
    int blc2 = blockIdx.x, tid = threadIdx.x;
    int bl = blc2 >> 5, op = blc2 & 31;
    int o0 = op * 2;
    const uint32_t* fp = g_fh + (size_t)blc2 * SW_;
    const float* bp0 = g_bias + (size_t)o0 * SW_;
    const float* bp1 = g_bias + (size_t)(o0 + 1) * SW_;
    float v0[16], v1[16];
    float sum0 = 0.f, sq0 = 0.f, sum1 = 0.f, sq1 = 0.f;
    #pragma unroll
    for (int k = 0; k < 16; k++) {
        int i = tid + 512*k;
        uint32_t u = fp[i];
        __half2 h = *(__half2*)&u;
        float2 f = __half22float2(h);
        float t0 = f.x + bp0[i];
        float t1 = f.y + bp1[i];
        v0[k] = t0; v1[k] = t1;
        sum0 += t0; sq0 += t0*t0;
        sum1 += t1; sq1 += t1*t1;
    }
    float ts0 = blockReduceSum(sum0, sbuf1);
    __syncthreads();
    float tq0 = blockReduceSum(sq0, sbuf2);
    __syncthreads();
    float ts1 = blockReduceSum(sum1, sbuf1);
    __syncthreads();
    float tq1 = blockReduceSum(sq1, sbuf2);
    if (tid == 0) {
        float mu0 = ts0 * (1.f / (float)SW_);
        float var0 = tq0 * (1.f / (float)SW_) - mu0*mu0;
        s_mu0 = mu0; s_r0 = rsqrtf(var0 + 1e-5f);
        float mu1 = ts1 * (1.f / (float)SW_);
        float var1 = tq1 * (1.f / (float)SW_) - mu1*mu1;
        s_mu1 = mu1; s_r1 = rsqrtf(var1 + 1e-5f);
    }
    __syncthreads();
    float mu0 = s_mu0, r0 = s_r0, mu1 = s_mu1, r1 = s_r1;
    const float* xp0 = x + ((size_t)bl*C_ + o0)*SW_;
    const float* xp1 = xp0 + SW_;
    float* op0 = out + ((size_t)bl*C_ + o0)*SW_;
    float* op1 = op0 + SW_;
    #pragma unroll
    for (int k = 0; k < 16; k++) {
        int i = tid + 512*k;
        float gg = lng[i], bb = lnb[i];
        op0[i] = (v0[k] - mu0) * r0 * gg + bb + xp0[i];
        op1[i] = (v1[k] - mu1) * r1 * gg + bb + xp1[i];
    }
}

// ---------------- launch ----------------
extern "C" void kernel_launch(void* const* d_in, const int* in_sizes, int n_in,
                              void* d_out, int out_size) {
    const float* x         = (const float*)d_in[0];
    const float* nu_log    = (const float*)d_in[1];
    const float* theta_log = (const float*)d_in[2];
    const float* disp_nu   = (const float*)d_in[3];
    const float* disp_th   = (const float*)d_in[4];
    const float* mlp_w1    = (const float*)d_in[5];
    const float* mlp_b1    = (const float*)d_in[6];
    const float* mlp_w2    = (const float*)d_in[7];
    const float* mlp_b2    = (const float*)d_in[8];
    const float* fscale    = (const float*)d_in[9];
    const float* U_row_r   = (const float*)d_in[10];
    const float* U_row_i   = (const float*)d_in[11];
    const float* V_col_r   = (const float*)d_in[12];
    const float* V_col_i   = (const float*)d_in[13];
    const float* proj_W_r  = (const float*)d_in[14];
    const float* proj_W_i  = (const float*)d_in[15];
    const float* proj_b_r  = (const float*)d_in[16];
    const float* proj_b_i  = (const float*)d_in[17];
    const float* convr_k   = (const float*)d_in[18];
    const float* convr_b   = (const float*)d_in[19];
    const float* convi_k   = (const float*)d_in[20];
    const float* convi_b   = (const float*)d_in[21];
    const float* fuse_k    = (const float*)d_in[22];
    const float* fuse_b    = (const float*)d_in[23];
    const float* ln_g      = (const float*)d_in[24];
    const float* ln_b      = (const float*)d_in[25];
    float* out = (float*)d_out;

    cudaFuncSetAttribute(k_u_prep,   cudaFuncAttributeMaxDynamicSharedMemorySize, SMEM_U_BYTES);
    cudaFuncSetAttribute(k_conv_mma, cudaFuncAttributeMaxDynamicSharedMemorySize, CONV_SMEM);

    k_u_prep<<<2112, 256, SMEM_U_BYTES>>>(x, U_row_r, U_row_i, V_col_r, V_col_i,
                                          fuse_k, convr_k, convi_k, convr_b, convi_b, fuse_b,
                                          proj_W_r, proj_W_i, proj_b_r, proj_b_i);
    k_scan<<<16, 256>>>(nu_log, theta_log, disp_nu, disp_th,
                        mlp_w1, mlp_b1, mlp_w2, mlp_b2, fscale);
    k_recon_mma<<<PLANES_, 256>>>(U_row_r, U_row_i, V_col_r, V_col_i);
    k_conv_mma<<<512, 512, CONV_SMEM>>>();
    k_ln<<<1024, 512>>>(x, ln_g, ln_b, out);
}

// round 13
// speedup vs baseline: 1.3247x; 1.1990x over previous
#include <cuda_runtime.h>
#include <cuda_fp16.h>
#include <math.h>
#include <stdint.h>

#define B_  2
#define L_  16
#define C_  64
#define S_  64
#define W_  128
#define R_  32
#define H_  32
#define BL_ (B_*L_)
#define SW_ (S_*W_)
#define CR_ (C_*R_)
#define PLANES_ (BL_*C_)
#define NELEM_ (PLANES_*SW_)

// ---------------- device scratch ----------------
__device__ float    g_ctx[BL_*C_];
__device__ float    g_u_re[BL_*CR_],  g_u_im[BL_*CR_];
__device__ float    g_h_re[BL_*CR_],  g_h_im[BL_*CR_];
__device__ uint32_t g_yh[NELEM_];       // half2 (re,im) planes
__device__ uint32_t g_fh[NELEM_/2];     // half2 (o, o+1) fused planes
__device__ __half   g_Bw[9*8192];       // per-tap swizzled [o=64][k=128] fp16 weights
__device__ float    g_bias[C_*SW_];     // bias + border-tap field

// ---------------- helpers ----------------
__device__ __forceinline__ float blockReduceSum(float v, float* sbuf) {
    int lane = threadIdx.x & 31, warp = threadIdx.x >> 5;
    #pragma unroll
    for (int o = 16; o > 0; o >>= 1) v += __shfl_down_sync(0xffffffffu, v, o);
    if (lane == 0) sbuf[warp] = v;
    __syncthreads();
    int nw = blockDim.x >> 5;
    v = (threadIdx.x < nw) ? sbuf[threadIdx.x] : 0.f;
    if (warp == 0) {
        #pragma unroll
        for (int o = 16; o > 0; o >>= 1) v += __shfl_down_sync(0xffffffffu, v, o);
    }
    return v;
}
__device__ __forceinline__ uint32_t smem_u32(const void* p) {
    uint32_t a;
    asm("{ .reg .u64 t; cvta.to.shared.u64 t, %1; cvt.u32.u64 %0, t; }" : "=r"(a) : "l"(p));
    return a;
}

// ---------------- K4+K0: u-projection MMA (blocks 0..2047) + prep (blocks 2048..2111) ----------------
#define SMEM_U_BYTES (16384 + 8192 + 32768 + 2048)
__global__ void __launch_bounds__(256) k_u_prep(const float* __restrict__ x,
        const float* __restrict__ Ur, const float* __restrict__ Ui,
        const float* __restrict__ Vr, const float* __restrict__ Vi,
        const float* __restrict__ fuse_k, const float* __restrict__ convr_k,
        const float* __restrict__ convi_k, const float* __restrict__ convr_b,
        const float* __restrict__ convi_b, const float* __restrict__ fuse_b,
        const float* __restrict__ Wr, const float* __restrict__ Wi,
        const float* __restrict__ br, const float* __restrict__ bi) {
    extern __shared__ __align__(16) char smu[];
    int tid = threadIdx.x, lane = tid & 31, warp = tid >> 5;

    if (blockIdx.x >= 2048) {
        // ======== prep branch ========
        int o = blockIdx.x - 2048;
        float* sF1 = (float*)smu;
        float* sF2 = sF1 + 64;
        float* sP  = sF2 + 64;
        float* sQ  = sP + 576;
        float* sA2 = sQ + 576;
        float* sB2 = sA2 + 576;
        float* sT  = sB2 + 576;
        float* sc0 = sT + 9;
        if (tid < 64)       sF1[tid]      = fuse_k[o*128 + tid];
        else if (tid < 128) sF2[tid - 64] = fuse_k[o*128 + tid];
        __syncthreads();
        for (int idx = tid; idx < 576; idx += 256) {
            float p = 0.f, q = 0.f;
            for (int m = 0; m < C_; m++) {
                p += sF1[m] * convr_k[m*576 + idx];
                q += sF2[m] * convi_k[m*576 + idx];
            }
            sP[idx] = p; sQ[idx] = q;
        }
        if (tid == 0) {
            float v = fuse_b[o];
            for (int m = 0; m < C_; m++) v += sF1[m]*convr_b[m] + sF2[m]*convi_b[m];
            *sc0 = v;
        }
        __syncthreads();
        for (int idx = tid; idx < 576; idx += 256) {
            int cp = idx / 9, t = idx % 9;
            float a = 0.f, bb = 0.f;
            for (int cc = 0; cc < C_; cc++) {
                float pp = sP[cc*9 + t], qq = sQ[cc*9 + t];
                float wr = Wr[cc*C_ + cp], wi = Wi[cc*C_ + cp];
                a  += pp * wr + qq * wi;
                bb += -pp * wi + qq * wr;
            }
            sA2[idx] = a; sB2[idx] = bb;
        }
        if (tid < 9) {
            float tt = 0.f;
            for (int cc = 0; cc < C_; cc++)
                tt += sP[cc*9 + tid]*br[cc] + sQ[cc*9 + tid]*bi[cc];
            sT[tid] = tt;
        }
        __syncthreads();
        for (int i = tid; i < 9*128; i += 256) {
            int tt = i >> 7, k = i & 127;
            int ci = k >> 1, reim = k & 1;
            float wv = reim ? sB2[ci*9 + tt] : sA2[ci*9 + tt];
            int chunk = k >> 3;
            g_Bw[tt*8192 + o*128 + ((chunk ^ (o & 7)) << 3) + (k & 7)] = __float2half(wv);
        }
        float T[9];
        #pragma unroll
        for (int k = 0; k < 9; k++) T[k] = sT[k];
        float c0 = *sc0;
        for (int i = tid; i < SW_; i += 256) {
            int s = i >> 7, w = i & 127;
            float b = c0;
            #pragma unroll
            for (int k = 0; k < 9; k++) {
                int ds = k/3 - 1, dw = k%3 - 1;
                if (((unsigned)(s + ds) < (unsigned)S_) && ((unsigned)(w + dw) < (unsigned)W_))
                    b += T[k];
            }
            g_bias[o*SW_ + i] = b;
        }
        return;
    }

    // ======== u-projection branch ========
    __half* sXT = (__half*)smu;
    __half* sUp = (__half*)(smu + 16384);
    float*  sV  = (float*)(smu + 16384 + 8192);
    float*  sred = (float*)(smu + 16384 + 8192 + 32768);
    int blc = blockIdx.x, c = blc & 63;

    const float* xp = x + (size_t)blc * SW_;
    float csum = 0.f;
    for (int i = tid; i < SW_; i += 256) {
        int s = i >> 7, w = i & 127;
        float xv = xp[i];
        csum += xv;
        int off = w*128 + ((((s >> 3) ^ (w & 7))) << 4) + (s & 7)*2;
        *(__half*)((char*)sXT + off) = __float2half(xv);
    }
    for (int i = tid; i < 64*64; i += 256) {
        int n = i >> 6, k = i & 63;
        int r = n >> 1;
        float v = Ur[c*2048 + k*32 + r];
        if (n & 1) v = -Ui[c*2048 + k*32 + r];
        int off = n*128 + ((((k >> 3) ^ (n & 7))) << 4) + (k & 7)*2;
        *(__half*)((char*)sUp + off) = __float2half(v);
    }
    for (int i = tid; i < W_*R_; i += 256) {
        sV[i*2]     = Vr[c*4096 + i];
        sV[i*2 + 1] = Vi[c*4096 + i];
    }
    csum = blockReduceSum(csum, sred);
    if (tid == 0) g_ctx[blc] = csum * (1.f / (float)SW_);
    __syncthreads();

    uint32_t sXu = smem_u32(sXT), sUu = smem_u32(sUp);
    int wbase = warp * 16;
    float acc[8][4];
    #pragma unroll
    for (int nt = 0; nt < 8; nt++)
        #pragma unroll
        for (int j = 0; j < 4; j++) acc[nt][j] = 0.f;

    #pragma unroll
    for (int ks = 0; ks < 4; ks++) {
        int row = wbase + (lane & 15);
        int cblk = ks*2 + (lane >> 4);
        uint32_t aaddr = sXu + row*128 + (uint32_t)((cblk ^ (row & 7)) << 4);
        uint32_t a0, a1, a2, a3;
        asm volatile("ldmatrix.sync.aligned.m8n8.x4.shared.b16 {%0,%1,%2,%3}, [%4];"
                     : "=r"(a0), "=r"(a1), "=r"(a2), "=r"(a3) : "r"(aaddr));
        #pragma unroll
        for (int np = 0; np < 4; np++) {
            int n = (np*2 + (lane >> 4))*8 + (lane & 7);
            int cb = ks*2 + ((lane >> 3) & 1);
            uint32_t baddr = sUu + n*128 + (uint32_t)((cb ^ (n & 7)) << 4);
            uint32_t b0, b1, b2, b3;
            asm volatile("ldmatrix.sync.aligned.m8n8.x4.shared.b16 {%0,%1,%2,%3}, [%4];"
                         : "=r"(b0), "=r"(b1), "=r"(b2), "=r"(b3) : "r"(baddr));
            asm volatile("mma.sync.aligned.m16n8k16.row.col.f32.f16.f16.f32 "
                         "{%0,%1,%2,%3}, {%4,%5,%6,%7}, {%8,%9}, {%0,%1,%2,%3};"
                         : "+f"(acc[np*2][0]), "+f"(acc[np*2][1]), "+f"(acc[np*2][2]), "+f"(acc[np*2][3])
                         : "r"(a0), "r"(a1), "r"(a2), "r"(a3), "r"(b0), "r"(b1));
            asm volatile("mma.sync.aligned.m16n8k16.row.col.f32.f16.f16.f32 "
                         "{%0,%1,%2,%3}, {%4,%5,%6,%7}, {%8,%9}, {%0,%1,%2,%3};"
                         : "+f"(acc[np*2+1][0]), "+f"(acc[np*2+1][1]), "+f"(acc[np*2+1][2]), "+f"(acc[np*2+1][3])
                         : "r"(a0), "r"(a1), "r"(a2), "r"(a3), "r"(b2), "r"(b3));
        }
    }
    int g = lane >> 2, tq = lane & 3;
    float pre[8], pim[8];
    #pragma unroll
    for (int nt = 0; nt < 8; nt++) { pre[nt] = 0.f; pim[nt] = 0.f; }
    {
        int w1 = wbase + g, w2 = w1 + 8;
        #pragma unroll
        for (int nt = 0; nt < 8; nt++) {
            int r = nt*4 + tq;
            float vr1 = sV[(w1*32 + r)*2], vi1 = sV[(w1*32 + r)*2 + 1];
            float vr2 = sV[(w2*32 + r)*2], vi2 = sV[(w2*32 + r)*2 + 1];
            float ar = acc[nt][0], ai = acc[nt][1];
            float br2 = acc[nt][2], bi2 = acc[nt][3];
            pre[nt] += ar*vr1 + ai*vi1 + br2*vr2 + bi2*vi2;
            pim[nt] += ai*vr1 - ar*vi1 + bi2*vr2 - br2*vi2;
        }
    }
    #pragma unroll
    for (int nt = 0; nt < 8; nt++) {
        #pragma unroll
        for (int o = 16; o >= 4; o >>= 1) {
            pre[nt] += __shfl_down_sync(0xffffffffu, pre[nt], o);
            pim[nt] += __shfl_down_sync(0xffffffffu, pim[nt], o);
        }
    }
    __syncthreads();
    if (lane < 4) {
        #pragma unroll
        for (int nt = 0; nt < 8; nt++) {
            int r = nt*4 + lane;
            sred[warp*64 + r*2]     = pre[nt];
            sred[warp*64 + r*2 + 1] = pim[nt];
        }
    }
    __syncthreads();
    if (tid < 32) {
        int r = tid;
        float ur = 0.f, ui = 0.f;
        #pragma unroll
        for (int wp = 0; wp < 8; wp++) {
            ur += sred[wp*64 + r*2];
            ui += sred[wp*64 + r*2 + 1];
        }
        g_u_re[blc*R_ + r] = ur;
        g_u_im[blc*R_ + r] = ui;
    }
}

// ---------------- K5: fused MLP + modulation + scan ----------------
__global__ void __launch_bounds__(256) k_scan(
        const float* __restrict__ nu_log, const float* __restrict__ th_log,
        const float* __restrict__ dnu, const float* __restrict__ dth,
        const float* __restrict__ w1, const float* __restrict__ b1,
        const float* __restrict__ w2, const float* __restrict__ b2,
        const float* __restrict__ fscale) {
    __shared__ float sctx[16*64];
    __shared__ float shid[16*32];
    int tid = threadIdx.x;
    int b = blockIdx.x >> 3, chunk = blockIdx.x & 7;
    int cr = chunk*256 + tid;

    for (int i = tid; i < 16*64; i += 256)
        sctx[i] = g_ctx[b*16*64 + i];
    __syncthreads();
    for (int idx = tid; idx < 512; idx += 256) {
        int l = idx >> 5, h = idx & 31;
        float v = b1[h];
        for (int cc = 0; cc < C_; cc++) v += sctx[l*64 + cc] * w1[cc*H_ + h];
        shid[l*32 + h] = tanhf(v);
    }
    __syncthreads();

    float fr[16], fi[16];
    float b2r = b2[2*cr], b2i = b2[2*cr + 1];
    #pragma unroll
    for (int l = 0; l < 16; l++) { fr[l] = b2r; fi[l] = b2i; }
    for (int j = 0; j < H_; j++) {
        float wr = w2[j*(CR_*2) + 2*cr];
        float wi = w2[j*(CR_*2) + 2*cr + 1];
        #pragma unroll
        for (int l = 0; l < 16; l++) {
            float hv = shid[l*32 + j];
            fr[l] = fmaf(hv, wr, fr[l]);
            fi[l] = fmaf(hv, wi, fi[l]);
        }
    }
    float fs = *fscale;
    float nu = expf(nu_log[cr] + dnu[cr]);
    float th = expf(th_log[cr] + dth[cr]);
    float el = expf(-nu);
    float ga = sqrtf(fmaxf(1.f - el*el, 1e-6f));
    float lr = el * cosf(th), li = el * sinf(th);
    float hr = 0.f, hi = 0.f;
    #pragma unroll
    for (int l = 0; l < L_; l++) {
        int idx = (b*L_ + l)*CR_ + cr;
        float mr = ga * (1.f + fs * fr[l]);
        float mi = ga * (fs * fi[l]);
        float ur_raw = g_u_re[idx], ui_raw = g_u_im[idx];
        float ur = mr*ur_raw - mi*ui_raw;
        float ui = mr*ui_raw + mi*ur_raw;
        float nr = lr*hr - li*hi + ur;
        float ni = lr*hi + li*hr + ui;
        hr = nr; hi = ni;
        g_h_re[idx] = hr;
        g_h_im[idx] = hi;
    }
}

// ---------------- K6: reconstruct via mma.sync -> half2 planes ----------------
__global__ void __launch_bounds__(256) k_recon_mma(
        const float* __restrict__ Ur, const float* __restrict__ Ui,
        const float* __restrict__ Vr, const float* __restrict__ Vi) {
    __shared__ __align__(16) __half sA[64*64];
    __shared__ __align__(16) __half sBv[256*64];
    __shared__ float sh[64];
    int tid = threadIdx.x, lane = tid & 31, warp = tid >> 5;
    int blc = blockIdx.x, c = blc & 63;
    if (tid < 64) sh[tid] = (tid < 32) ? g_h_re[blc*R_ + tid] : g_h_im[blc*R_ + tid - 32];
    __syncthreads();
    for (int i = tid; i < 2048; i += 256) {
        int s = i >> 5, r = i & 31;
        float hr = sh[r], hi = sh[32 + r];
        float ur = Ur[c*2048 + s*32 + r], ui = Ui[c*2048 + s*32 + r];
        float gr = hr*ur - hi*ui;
        float gi = hr*ui + hi*ur;
        int off = s*128 + ((((r >> 2) ^ (s & 7))) << 4) + (r & 3)*4;
        __half2 h2 = __floats2half2_rn(gr, gi);
        *(uint32_t*)((char*)sA + off) = *(uint32_t*)&h2;
    }
    for (int i = tid; i < 256*64; i += 256) {
        int n = i >> 6, k = i & 63;
        int w = n >> 1, nc = n & 1, r = k >> 1, kc = k & 1;
        float vr = Vr[c*4096 + w*32 + r], vi = Vi[c*4096 + w*32 + r];
        float v = nc ? (kc ? vr : vi) : (kc ? -vi : vr);
        int off = n*128 + ((((k >> 3) ^ (n & 7))) << 4) + (k & 7)*2;
        *(__half*)((char*)sBv + off) = __float2half(v);
    }
    __syncthreads();

    uint32_t sAu = smem_u32(sA), sBu = smem_u32(sBv);
    int mt = warp & 3, nh = warp >> 2;
    int mrow = mt * 16;
    float acc[16][4];
    #pragma unroll
    for (int nt = 0; nt < 16; nt++)
        #pragma unroll
        for (int j = 0; j < 4; j++) acc[nt][j] = 0.f;

    #pragma unroll
    for (int ks = 0; ks < 4; ks++) {
        int row = mrow + (lane & 15);
        int cblk = ks*2 + (lane >> 4);
        uint32_t aaddr = sAu + row*128 + (uint32_t)((cblk ^ (row & 7)) << 4);
        uint32_t a0, a1, a2, a3;
        asm volatile("ldmatrix.sync.aligned.m8n8.x4.shared.b16 {%0,%1,%2,%3}, [%4];"
                     : "=r"(a0), "=r"(a1), "=r"(a2), "=r"(a3) : "r"(aaddr));
        #pragma unroll
        for (int np = 0; np < 8; np++) {
            int n = (nh*16 + np*2 + (lane >> 4))*8 + (lane & 7);
            int cb = ks*2 + ((lane >> 3) & 1);
            uint32_t baddr = sBu + n*128 + (uint32_t)((cb ^ (n & 7)) << 4);
            uint32_t b0, b1, b2, b3;
            asm volatile("ldmatrix.sync.aligned.m8n8.x4.shared.b16 {%0,%1,%2,%3}, [%4];"
                         : "=r"(b0), "=r"(b1), "=r"(b2), "=r"(b3) : "r"(baddr));
            asm volatile("mma.sync.aligned.m16n8k16.row.col.f32.f16.f16.f32 "
                         "{%0,%1,%2,%3}, {%4,%5,%6,%7}, {%8,%9}, {%0,%1,%2,%3};"
                         : "+f"(acc[np*2][0]), "+f"(acc[np*2][1]), "+f"(acc[np*2][2]), "+f"(acc[np*2][3])
                         : "r"(a0), "r"(a1), "r"(a2), "r"(a3), "r"(b0), "r"(b1));
            asm volatile("mma.sync.aligned.m16n8k16.row.col.f32.f16.f16.f32 "
                         "{%0,%1,%2,%3}, {%4,%5,%6,%7}, {%8,%9}, {%0,%1,%2,%3};"
                         : "+f"(acc[np*2+1][0]), "+f"(acc[np*2+1][1]), "+f"(acc[np*2+1][2]), "+f"(acc[np*2+1][3])
                         : "r"(a0), "r"(a1), "r"(a2), "r"(a3), "r"(b2), "r"(b3));
        }
    }
    int g = lane >> 2, tq = lane & 3;
    uint32_t* py = g_yh + (size_t)blc*SW_;
    #pragma unroll
    for (int nt = 0; nt < 16; nt++) {
        int w = (nh*16 + nt)*4 + tq;
        __half2 h1 = __floats2half2_rn(acc[nt][0], acc[nt][1]);
        __half2 h2 = __floats2half2_rn(acc[nt][2], acc[nt][3]);
        py[(mrow + g)*W_ + w]     = *(uint32_t*)&h1;
        py[(mrow + g + 8)*W_ + w] = *(uint32_t*)&h2;
    }
}

// ---------------- K8: fp16 mma.sync conv-GEMM, register-pipelined double-buffered B ----------------
// SMEM: staged rows [6][130][64] half2 swz (199680) + 2x B tap tile (32768)
#define CONV_SMEM (199680 + 32768)
__global__ void __launch_bounds__(512) k_conv_mma() {
    extern __shared__ __align__(16) char smc[];
    char* sB = smc + 199680;
    int tid = threadIdx.x, lane = tid & 31, warp = tid >> 5;
    int bl = blockIdx.x >> 4, s0 = (blockIdx.x & 15) * 4;

    // stage 6 halo rows (R10 layout/loop — known good)
    const uint32_t* ybl = g_yh + (size_t)bl * (C_*SW_);
    for (int i = tid; i < 6*130*64; i += 512) {
        int ci = i / 780, rem = i % 780;
        int ds = rem / 130, pw = rem % 130;
        int sr = s0 + ds - 1, w = pw - 1;
        uint32_t v = 0u;
        if (((unsigned)sr < (unsigned)S_) && ((unsigned)w < (unsigned)W_))
            v = ybl[(size_t)ci*SW_ + sr*W_ + w];
        int phys = ds*33280 + pw*256 + ((((ci >> 2) ^ (pw & 7))) << 4) + (ci & 3)*4;
        *(uint32_t*)(smc + phys) = v;
    }
    // copy B tap 0 into buffer 0
    const uint4* bw4 = (const uint4*)g_Bw;
    {
        uint4* dst = (uint4*)sB;
        dst[tid]       = bw4[tid];
        dst[tid + 512] = bw4[tid + 512];
    }
    __syncthreads();

    float acc[2][8][4];
    #pragma unroll
    for (int mt = 0; mt < 2; mt++)
        #pragma unroll
        for (int nt = 0; nt < 8; nt++)
            #pragma unroll
            for (int j = 0; j < 4; j++) acc[mt][nt][j] = 0.f;

    uint32_t sAu = smem_u32(smc), sBu = smem_u32(sB);
    int s_row = warp >> 2;
    int wbase = (warp & 3) * 32;

    #pragma unroll 1
    for (int t = 0; t < 9; t++) {
        // prefetch next tap's B into registers (LDG issued before compute)
        uint4 p0, p1;
        if (t < 8) {
            p0 = bw4[(t + 1)*1024 + tid];
            p1 = bw4[(t + 1)*1024 + tid + 512];
        }
        uint32_t sBt = sBu + (uint32_t)((t & 1)*16384);
        int tx = t % 3, ds = s_row + t / 3;
        #pragma unroll 1
        for (int ks = 0; ks < 8; ks++) {
            uint32_t a0[2], a1[2], a2[2], a3[2];
            #pragma unroll
            for (int mt = 0; mt < 2; mt++) {
                int row = wbase + mt*16 + (lane & 15) + tx;
                int cblk = ks*2 + (lane >> 4);
                uint32_t aaddr = sAu + ds*33280 + row*256 + (uint32_t)((cblk ^ (row & 7)) << 4);
                asm volatile("ldmatrix.sync.aligned.m8n8.x4.shared.b16 {%0,%1,%2,%3}, [%4];"
                             : "=r"(a0[mt]), "=r"(a1[mt]), "=r"(a2[mt]), "=r"(a3[mt]) : "r"(aaddr));
            }
            #pragma unroll
            for (int np = 0; np < 4; np++) {
                int n = (np*2 + (lane >> 4))*8 + (lane & 7);
                int cb = ks*2 + ((lane >> 3) & 1);
                uint32_t baddr = sBt + n*256 + (uint32_t)((cb ^ (n & 7)) << 4);
                uint32_t b0, b1, b2, b3;
                asm volatile("ldmatrix.sync.aligned.m8n8.x4.shared.b16 {%0,%1,%2,%3}, [%4];"
                             : "=r"(b0), "=r"(b1), "=r"(b2), "=r"(b3) : "r"(baddr));
                #pragma unroll
                for (int mt = 0; mt < 2; mt++) {
                    asm volatile("mma.sync.aligned.m16n8k16.row.col.f32.f16.f16.f32 "
                                 "{%0,%1,%2,%3}, {%4,%5,%6,%7}, {%8,%9}, {%0,%1,%2,%3};"
                                 : "+f"(acc[mt][np*2][0]), "+f"(acc[mt][np*2][1]),
                                   "+f"(acc[mt][np*2][2]), "+f"(acc[mt][np*2][3])
                                 : "r"(a0[mt]), "r"(a1[mt]), "r"(a2[mt]), "r"(a3[mt]),
                                   "r"(b0), "r"(b1));
                    asm volatile("mma.sync.aligned.m16n8k16.row.col.f32.f16.f16.f32 "
                                 "{%0,%1,%2,%3}, {%4,%5,%6,%7}, {%8,%9}, {%0,%1,%2,%3};"
                                 : "+f"(acc[mt][np*2+1][0]), "+f"(acc[mt][np*2+1][1]),
                                   "+f"(acc[mt][np*2+1][2]), "+f"(acc[mt][np*2+1][3])
                                 : "r"(a0[mt]), "r"(a1[mt]), "r"(a2[mt]), "r"(a3[mt]),
                                   "r"(b2), "r"(b3));
                }
            }
        }
        // store prefetched B into the other buffer, then one sync
        if (t < 8) {
            uint4* dst = (uint4*)(sB + ((t + 1) & 1)*16384);
            dst[tid]       = p0;
            dst[tid + 512] = p1;
            __syncthreads();
        }
    }
    int g = lane >> 2, tq = lane & 3;
    #pragma unroll
    for (int mt = 0; mt < 2; mt++) {
        uint32_t* ob = g_fh + (size_t)bl * (32*SW_) + (s0 + s_row)*W_ + wbase + mt*16 + g;
        #pragma unroll
        for (int nt = 0; nt < 8; nt++) {
            int pi = nt*4 + tq;
            __half2 hA = __floats2half2_rn(acc[mt][nt][0], acc[mt][nt][1]);
            __half2 hB = __floats2half2_rn(acc[mt][nt][2], acc[mt][nt][3]);
            ob[(size_t)pi*SW_]     = *(uint32_t*)&hA;
            ob[(size_t)pi*SW_ + 8] = *(uint32_t*)&hB;
        }
    }
}

// ---------------- K9: LayerNorm over o-pairs (+ bias) + residual ----------------
__global__ void __launch_bounds__(512) k_ln(const float* __restrict__ x,
                     const float* __restrict__ lng,
                     const float* __restrict__ lnb, float* __restrict__ out) {
    __shared__ float sbuf1[16], sbuf2[16];
    __shared__ float s_mu0, s_r0, s_mu1, s_r1;
    int blc2 = blockIdx.x, tid = threadIdx.x;
    int bl = blc2 >> 5, op = blc2 & 31;
    int o0 = op * 2;
    const uint32_t* fp = g_fh + (size_t)blc2 * SW_;
    const float* bp0 = g_bias + (size_t)o0 * SW_;
    const float* bp1 = g_bias + (size_t)(o0 + 1) * SW_;
    float v0[16], v1[16];
    float sum0 = 0.f, sq0 = 0.f, sum1 = 0.f, sq1 = 0.f;
    #pragma unroll
    for (int k = 0; k < 16; k++) {
        int i = tid + 512*k;
        uint32_t u = fp[i];
        __half2 h = *(__half2*)&u;
        float2 f = __half22float2(h);
        float t0 = f.x + bp0[i];
        float t1 = f.y + bp1[i];
        v0[k] = t0; v1[k] = t1;
        sum0 += t0; sq0 += t0*t0;
        sum1 += t1; sq1 += t1*t1;
    }
    float ts0 = blockReduceSum(sum0, sbuf1);
    __syncthreads();
    float tq0 = blockReduceSum(sq0, sbuf2);
    __syncthreads();
    float ts1 = blockReduceSum(sum1, sbuf1);
    __syncthreads();
    float tq1 = blockReduceSum(sq1, sbuf2);
    if (tid == 0) {
        float mu0 = ts0 * (1.f / (float)SW_);
        float var0 = tq0 * (1.f / (float)SW_) - mu0*mu0;
        s_mu0 = mu0; s_r0 = rsqrtf(var0 + 1e-5f);
        float mu1 = ts1 * (1.f / (float)SW_);
        float var1 = tq1 * (1.f / (float)SW_) - mu1*mu1;
        s_mu1 = mu1; s_r1 = rsqrtf(var1 + 1e-5f);
    }
    __syncthreads();
    float mu0 = s_mu0, r0 = s_r0, mu1 = s_mu1, r1 = s_r1;
    const float* xp0 = x + ((size_t)bl*C_ + o0)*SW_;
    const float* xp1 = xp0 + SW_;
    float* op0 = out + ((size_t)bl*C_ + o0)*SW_;
    float* op1 = op0 + SW_;
    #pragma unroll
    for (int k = 0; k < 16; k++) {
        int i = tid + 512*k;
        float gg = lng[i], bb = lnb[i];
        op0[i] = (v0[k] - mu0) * r0 * gg + bb + xp0[i];
        op1[i] = (v1[k] - mu1) * r1 * gg + bb + xp1[i];
    }
}

// ---------------- launch ----------------
extern "C" void kernel_launch(void* const* d_in, const int* in_sizes, int n_in,
                              void* d_out, int out_size) {
    const float* x         = (const float*)d_in[0];
    const float* nu_log    = (const float*)d_in[1];
    const float* theta_log = (const float*)d_in[2];
    const float* disp_nu   = (const float*)d_in[3];
    const float* disp_th   = (const float*)d_in[4];
    const float* mlp_w1    = (const float*)d_in[5];
    const float* mlp_b1    = (const float*)d_in[6];
    const float* mlp_w2    = (const float*)d_in[7];
    const float* mlp_b2    = (const float*)d_in[8];
    const float* fscale    = (const float*)d_in[9];
    const float* U_row_r   = (const float*)d_in[10];
    const float* U_row_i   = (const float*)d_in[11];
    const float* V_col_r   = (const float*)d_in[12];
    const float* V_col_i   = (const float*)d_in[13];
    const float* proj_W_r  = (const float*)d_in[14];
    const float* proj_W_i  = (const float*)d_in[15];
    const float* proj_b_r  = (const float*)d_in[16];
    const float* proj_b_i  = (const float*)d_in[17];
    const float* convr_k   = (const float*)d_in[18];
    const float* convr_b   = (const float*)d_in[19];
    const float* convi_k   = (const float*)d_in[20];
    const float* convi_b   = (const float*)d_in[21];
    const float* fuse_k    = (const float*)d_in[22];
    const float* fuse_b    = (const float*)d_in[23];
    const float* ln_g      = (const float*)d_in[24];
    const float* ln_b      = (const float*)d_in[25];
    float* out = (float*)d_out;

    cudaFuncSetAttribute(k_u_prep,   cudaFuncAttributeMaxDynamicSharedMemorySize, SMEM_U_BYTES);
    cudaFuncSetAttribute(k_conv_mma, cudaFuncAttributeMaxDynamicSharedMemorySize, CONV_SMEM);

    k_u_prep<<<2112, 256, SMEM_U_BYTES>>>(x, U_row_r, U_row_i, V_col_r, V_col_i,
                                          fuse_k, convr_k, convi_k, convr_b, convi_b, fuse_b,
                                          proj_W_r, proj_W_i, proj_b_r, proj_b_i);
    k_scan<<<16, 256>>>(nu_log, theta_log, disp_nu, disp_th,
                        mlp_w1, mlp_b1, mlp_w2, mlp_b2, fscale);
    k_recon_mma<<<PLANES_, 256>>>(U_row_r, U_row_i, V_col_r, V_col_i);
    k_conv_mma<<<512, 512, CONV_SMEM>>>();
    k_ln<<<1024, 512>>>(x, ln_g, ln_b, out);
}

// round 14
// speedup vs baseline: 1.3605x; 1.0270x over previous
#include <cuda_runtime.h>
#include <cuda_fp16.h>
#include <math.h>
#include <stdint.h>

#define B_  2
#define L_  16
#define C_  64
#define S_  64
#define W_  128
#define R_  32
#define H_  32
#define BL_ (B_*L_)
#define SW_ (S_*W_)
#define CR_ (C_*R_)
#define PLANES_ (BL_*C_)
#define NELEM_ (PLANES_*SW_)

// ---------------- device scratch ----------------
__device__ float    g_ctx[BL_*C_];
__device__ float    g_u_re[BL_*CR_],  g_u_im[BL_*CR_];
__device__ float    g_h_re[BL_*CR_],  g_h_im[BL_*CR_];
__device__ uint32_t g_yh[NELEM_];       // half2 (re,im) planes
__device__ uint32_t g_fh[NELEM_/2];     // half2 (o, o+1) fused planes
__device__ __half   g_Bw[9*8192];       // per-tap swizzled [o=64][k=128] fp16 weights
__device__ float    g_bias[C_*SW_];     // bias + border-tap field

// ---------------- helpers ----------------
__device__ __forceinline__ float blockReduceSum(float v, float* sbuf) {
    int lane = threadIdx.x & 31, warp = threadIdx.x >> 5;
    #pragma unroll
    for (int o = 16; o > 0; o >>= 1) v += __shfl_down_sync(0xffffffffu, v, o);
    if (lane == 0) sbuf[warp] = v;
    __syncthreads();
    int nw = blockDim.x >> 5;
    v = (threadIdx.x < nw) ? sbuf[threadIdx.x] : 0.f;
    if (warp == 0) {
        #pragma unroll
        for (int o = 16; o > 0; o >>= 1) v += __shfl_down_sync(0xffffffffu, v, o);
    }
    return v;
}
__device__ __forceinline__ uint32_t smem_u32(const void* p) {
    uint32_t a;
    asm("{ .reg .u64 t; cvta.to.shared.u64 t, %1; cvt.u32.u64 %0, t; }" : "=r"(a) : "l"(p));
    return a;
}

// ---------------- K4+K0: u-projection MMA (blocks 0..2047) + prep (blocks 2048..2111) ----------------
#define SMEM_U_BYTES (16384 + 8192 + 32768 + 2048)
__global__ void __launch_bounds__(256) k_u_prep(const float* __restrict__ x,
        const float* __restrict__ Ur, const float* __restrict__ Ui,
        const float* __restrict__ Vr, const float* __restrict__ Vi,
        const float* __restrict__ fuse_k, const float* __restrict__ convr_k,
        const float* __restrict__ convi_k, const float* __restrict__ convr_b,
        const float* __restrict__ convi_b, const float* __restrict__ fuse_b,
        const float* __restrict__ Wr, const float* __restrict__ Wi,
        const float* __restrict__ br, const float* __restrict__ bi) {
    extern __shared__ __align__(16) char smu[];
    int tid = threadIdx.x, lane = tid & 31, warp = tid >> 5;

    if (blockIdx.x >= 2048) {
        // ======== prep branch ========
        int o = blockIdx.x - 2048;
        float* sF1 = (float*)smu;
        float* sF2 = sF1 + 64;
        float* sP  = sF2 + 64;
        float* sQ  = sP + 576;
        float* sA2 = sQ + 576;
        float* sB2 = sA2 + 576;
        float* sT  = sB2 + 576;
        float* sc0 = sT + 9;
        if (tid < 64)       sF1[tid]      = fuse_k[o*128 + tid];
        else if (tid < 128) sF2[tid - 64] = fuse_k[o*128 + tid];
        __syncthreads();
        for (int idx = tid; idx < 576; idx += 256) {
            float p = 0.f, q = 0.f;
            for (int m = 0; m < C_; m++) {
                p += sF1[m] * convr_k[m*576 + idx];
                q += sF2[m] * convi_k[m*576 + idx];
            }
            sP[idx] = p; sQ[idx] = q;
        }
        if (tid == 0) {
            float v = fuse_b[o];
            for (int m = 0; m < C_; m++) v += sF1[m]*convr_b[m] + sF2[m]*convi_b[m];
            *sc0 = v;
        }
        __syncthreads();
        for (int idx = tid; idx < 576; idx += 256) {
            int cp = idx / 9, t = idx % 9;
            float a = 0.f, bb = 0.f;
            for (int cc = 0; cc < C_; cc++) {
                float pp = sP[cc*9 + t], qq = sQ[cc*9 + t];
                float wr = Wr[cc*C_ + cp], wi = Wi[cc*C_ + cp];
                a  += pp * wr + qq * wi;
                bb += -pp * wi + qq * wr;
            }
            sA2[idx] = a; sB2[idx] = bb;
        }
        if (tid < 9) {
            float tt = 0.f;
            for (int cc = 0; cc < C_; cc++)
                tt += sP[cc*9 + tid]*br[cc] + sQ[cc*9 + tid]*bi[cc];
            sT[tid] = tt;
        }
        __syncthreads();
        for (int i = tid; i < 9*128; i += 256) {
            int tt = i >> 7, k = i & 127;
            int ci = k >> 1, reim = k & 1;
            float wv = reim ? sB2[ci*9 + tt] : sA2[ci*9 + tt];
            int chunk = k >> 3;
            g_Bw[tt*8192 + o*128 + ((chunk ^ (o & 7)) << 3) + (k & 7)] = __float2half(wv);
        }
        float T[9];
        #pragma unroll
        for (int k = 0; k < 9; k++) T[k] = sT[k];
        float c0 = *sc0;
        for (int i = tid; i < SW_; i += 256) {
            int s = i >> 7, w = i & 127;
            float b = c0;
            #pragma unroll
            for (int k = 0; k < 9; k++) {
                int ds = k/3 - 1, dw = k%3 - 1;
                if (((unsigned)(s + ds) < (unsigned)S_) && ((unsigned)(w + dw) < (unsigned)W_))
                    b += T[k];
            }
            g_bias[o*SW_ + i] = b;
        }
        return;
    }

    // ======== u-projection branch ========
    __half* sXT = (__half*)smu;
    __half* sUp = (__half*)(smu + 16384);
    float*  sV  = (float*)(smu + 16384 + 8192);
    float*  sred = (float*)(smu + 16384 + 8192 + 32768);
    int blc = blockIdx.x, c = blc & 63;

    // stage x^T: paired s rows -> 4B half2 stores (conflict-lean, no sub-word RMW)
    const float* xp = x + (size_t)blc * SW_;
    float csum = 0.f;
    for (int i = tid; i < 4096; i += 256) {
        int s2 = i >> 7, w = i & 127;
        int s = s2 * 2;
        float xv0 = xp[s*W_ + w];
        float xv1 = xp[s*W_ + W_ + w];
        csum += xv0 + xv1;
        int off = w*128 + ((((s >> 3) ^ (w & 7))) << 4) + (s & 7)*2;
        __half2 h2 = __floats2half2_rn(xv0, xv1);
        *(uint32_t*)((char*)sXT + off) = *(uint32_t*)&h2;
    }
    // stage U' [n][k]: paired k -> 4B stores
    for (int i = tid; i < 2048; i += 256) {
        int n = i >> 5, kp = i & 31;
        int k = kp * 2, r = n >> 1;
        float v0, v1;
        if (n & 1) {
            v0 = -Ui[c*2048 + k*32 + r];
            v1 = -Ui[c*2048 + (k + 1)*32 + r];
        } else {
            v0 = Ur[c*2048 + k*32 + r];
            v1 = Ur[c*2048 + (k + 1)*32 + r];
        }
        int off = n*128 + ((((k >> 3) ^ (n & 7))) << 4) + (k & 7)*2;
        __half2 h2 = __floats2half2_rn(v0, v1);
        *(uint32_t*)((char*)sUp + off) = *(uint32_t*)&h2;
    }
    for (int i = tid; i < W_*R_; i += 256) {
        sV[i*2]     = Vr[c*4096 + i];
        sV[i*2 + 1] = Vi[c*4096 + i];
    }
    csum = blockReduceSum(csum, sred);
    if (tid == 0) g_ctx[blc] = csum * (1.f / (float)SW_);
    __syncthreads();

    uint32_t sXu = smem_u32(sXT), sUu = smem_u32(sUp);
    int wbase = warp * 16;
    float acc[8][4];
    #pragma unroll
    for (int nt = 0; nt < 8; nt++)
        #pragma unroll
        for (int j = 0; j < 4; j++) acc[nt][j] = 0.f;

    #pragma unroll
    for (int ks = 0; ks < 4; ks++) {
        int row = wbase + (lane & 15);
        int cblk = ks*2 + (lane >> 4);
        uint32_t aaddr = sXu + row*128 + (uint32_t)((cblk ^ (row & 7)) << 4);
        uint32_t a0, a1, a2, a3;
        asm volatile("ldmatrix.sync.aligned.m8n8.x4.shared.b16 {%0,%1,%2,%3}, [%4];"
                     : "=r"(a0), "=r"(a1), "=r"(a2), "=r"(a3) : "r"(aaddr));
        #pragma unroll
        for (int np = 0; np < 4; np++) {
            int n = (np*2 + (lane >> 4))*8 + (lane & 7);
            int cb = ks*2 + ((lane >> 3) & 1);
            uint32_t baddr = sUu + n*128 + (uint32_t)((cb ^ (n & 7)) << 4);
            uint32_t b0, b1, b2, b3;
            asm volatile("ldmatrix.sync.aligned.m8n8.x4.shared.b16 {%0,%1,%2,%3}, [%4];"
                         : "=r"(b0), "=r"(b1), "=r"(b2), "=r"(b3) : "r"(baddr));
            asm volatile("mma.sync.aligned.m16n8k16.row.col.f32.f16.f16.f32 "
                         "{%0,%1,%2,%3}, {%4,%5,%6,%7}, {%8,%9}, {%0,%1,%2,%3};"
                         : "+f"(acc[np*2][0]), "+f"(acc[np*2][1]), "+f"(acc[np*2][2]), "+f"(acc[np*2][3])
                         : "r"(a0), "r"(a1), "r"(a2), "r"(a3), "r"(b0), "r"(b1));
            asm volatile("mma.sync.aligned.m16n8k16.row.col.f32.f16.f16.f32 "
                         "{%0,%1,%2,%3}, {%4,%5,%6,%7}, {%8,%9}, {%0,%1,%2,%3};"
                         : "+f"(acc[np*2+1][0]), "+f"(acc[np*2+1][1]), "+f"(acc[np*2+1][2]), "+f"(acc[np*2+1][3])
                         : "r"(a0), "r"(a1), "r"(a2), "r"(a3), "r"(b2), "r"(b3));
        }
    }
    int g = lane >> 2, tq = lane & 3;
    float pre[8], pim[8];
    #pragma unroll
    for (int nt = 0; nt < 8; nt++) { pre[nt] = 0.f; pim[nt] = 0.f; }
    {
        int w1 = wbase + g, w2 = w1 + 8;
        #pragma unroll
        for (int nt = 0; nt < 8; nt++) {
            int r = nt*4 + tq;
            float vr1 = sV[(w1*32 + r)*2], vi1 = sV[(w1*32 + r)*2 + 1];
            float vr2 = sV[(w2*32 + r)*2], vi2 = sV[(w2*32 + r)*2 + 1];
            float ar = acc[nt][0], ai = acc[nt][1];
            float br2 = acc[nt][2], bi2 = acc[nt][3];
            pre[nt] += ar*vr1 + ai*vi1 + br2*vr2 + bi2*vi2;
            pim[nt] += ai*vr1 - ar*vi1 + bi2*vr2 - br2*vi2;
        }
    }
    #pragma unroll
    for (int nt = 0; nt < 8; nt++) {
        #pragma unroll
        for (int o = 16; o >= 4; o >>= 1) {
            pre[nt] += __shfl_down_sync(0xffffffffu, pre[nt], o);
            pim[nt] += __shfl_down_sync(0xffffffffu, pim[nt], o);
        }
    }
    __syncthreads();
    if (lane < 4) {
        #pragma unroll
        for (int nt = 0; nt < 8; nt++) {
            int r = nt*4 + lane;
            sred[warp*64 + r*2]     = pre[nt];
            sred[warp*64 + r*2 + 1] = pim[nt];
        }
    }
    __syncthreads();
    if (tid < 32) {
        int r = tid;
        float ur = 0.f, ui = 0.f;
        #pragma unroll
        for (int wp = 0; wp < 8; wp++) {
            ur += sred[wp*64 + r*2];
            ui += sred[wp*64 + r*2 + 1];
        }
        g_u_re[blc*R_ + r] = ur;
        g_u_im[blc*R_ + r] = ui;
    }
}

// ---------------- K5: fused MLP + modulation + scan ----------------
__global__ void __launch_bounds__(256) k_scan(
        const float* __restrict__ nu_log, const float* __restrict__ th_log,
        const float* __restrict__ dnu, const float* __restrict__ dth,
        const float* __restrict__ w1, const float* __restrict__ b1,
        const float* __restrict__ w2, const float* __restrict__ b2,
        const float* __restrict__ fscale) {
    __shared__ float sctx[16*64];
    __shared__ float shid[16*32];
    int tid = threadIdx.x;
    int b = blockIdx.x >> 3, chunk = blockIdx.x & 7;
    int cr = chunk*256 + tid;

    for (int i = tid; i < 16*64; i += 256)
        sctx[i] = g_ctx[b*16*64 + i];
    __syncthreads();
    for (int idx = tid; idx < 512; idx += 256) {
        int l = idx >> 5, h = idx & 31;
        float v = b1[h];
        for (int cc = 0; cc < C_; cc++) v += sctx[l*64 + cc] * w1[cc*H_ + h];
        shid[l*32 + h] = tanhf(v);
    }
    __syncthreads();

    float fr[16], fi[16];
    float b2r = b2[2*cr], b2i = b2[2*cr + 1];
    #pragma unroll
    for (int l = 0; l < 16; l++) { fr[l] = b2r; fi[l] = b2i; }
    for (int j = 0; j < H_; j++) {
        float wr = w2[j*(CR_*2) + 2*cr];
        float wi = w2[j*(CR_*2) + 2*cr + 1];
        #pragma unroll
        for (int l = 0; l < 16; l++) {
            float hv = shid[l*32 + j];
            fr[l] = fmaf(hv, wr, fr[l]);
            fi[l] = fmaf(hv, wi, fi[l]);
        }
    }
    float fs = *fscale;
    float nu = expf(nu_log[cr] + dnu[cr]);
    float th = expf(th_log[cr] + dth[cr]);
    float el = expf(-nu);
    float ga = sqrtf(fmaxf(1.f - el*el, 1e-6f));
    float lr = el * cosf(th), li = el * sinf(th);
    float hr = 0.f, hi = 0.f;
    #pragma unroll
    for (int l = 0; l < L_; l++) {
        int idx = (b*L_ + l)*CR_ + cr;
        float mr = ga * (1.f + fs * fr[l]);
        float mi = ga * (fs * fi[l]);
        float ur_raw = g_u_re[idx], ui_raw = g_u_im[idx];
        float ur = mr*ur_raw - mi*ui_raw;
        float ui = mr*ui_raw + mi*ur_raw;
        float nr = lr*hr - li*hi + ur;
        float ni = lr*hi + li*hr + ui;
        hr = nr; hi = ni;
        g_h_re[idx] = hr;
        g_h_im[idx] = hi;
    }
}

// ---------------- K6: reconstruct via mma.sync -> half2 planes ----------------
__global__ void __launch_bounds__(256) k_recon_mma(
        const float* __restrict__ Ur, const float* __restrict__ Ui,
        const float* __restrict__ Vr, const float* __restrict__ Vi) {
    __shared__ __align__(16) __half sA[64*64];
    __shared__ __align__(16) __half sBv[256*64];
    __shared__ float sh[64];
    int tid = threadIdx.x, lane = tid & 31, warp = tid >> 5;
    int blc = blockIdx.x, c = blc & 63;
    if (tid < 64) sh[tid] = (tid < 32) ? g_h_re[blc*R_ + tid] : g_h_im[blc*R_ + tid - 32];
    __syncthreads();
    for (int i = tid; i < 2048; i += 256) {
        int s = i >> 5, r = i & 31;
        float hr = sh[r], hi = sh[32 + r];
        float ur = Ur[c*2048 + s*32 + r], ui = Ui[c*2048 + s*32 + r];
        float gr = hr*ur - hi*ui;
        float gi = hr*ui + hi*ur;
        int off = s*128 + ((((r >> 2) ^ (s & 7))) << 4) + (r & 3)*4;
        __half2 h2 = __floats2half2_rn(gr, gi);
        *(uint32_t*)((char*)sA + off) = *(uint32_t*)&h2;
    }
    // B tile: packed half2 per (n, r): nc=0 -> (Vr, -Vi), nc=1 -> (Vi, Vr)
    for (int i = tid; i < 8192; i += 256) {
        int n = i >> 5, r = i & 31;
        int w = n >> 1, nc = n & 1;
        float vr = Vr[c*4096 + w*32 + r], vi = Vi[c*4096 + w*32 + r];
        __half2 h2 = nc ? __floats2half2_rn(vi, vr) : __floats2half2_rn(vr, -vi);
        int off = n*128 + ((((r >> 2) ^ (n & 7))) << 4) + (r & 3)*4;
        *(uint32_t*)((char*)sBv + off) = *(uint32_t*)&h2;
    }
    __syncthreads();

    uint32_t sAu = smem_u32(sA), sBu = smem_u32(sBv);
    int mt = warp & 3, nh = warp >> 2;
    int mrow = mt * 16;
    float acc[16][4];
    #pragma unroll
    for (int nt = 0; nt < 16; nt++)
        #pragma unroll
        for (int j = 0; j < 4; j++) acc[nt][j] = 0.f;

    #pragma unroll
    for (int ks = 0; ks < 4; ks++) {
        int row = mrow + (lane & 15);
        int cblk = ks*2 + (lane >> 4);
        uint32_t aaddr = sAu + row*128 + (uint32_t)((cblk ^ (row & 7)) << 4);
        uint32_t a0, a1, a2, a3;
        asm volatile("ldmatrix.sync.aligned.m8n8.x4.shared.b16 {%0,%1,%2,%3}, [%4];"
                     : "=r"(a0), "=r"(a1), "=r"(a2), "=r"(a3) : "r"(aaddr));
        #pragma unroll
        for (int np = 0; np < 8; np++) {
            int n = (nh*16 + np*2 + (lane >> 4))*8 + (lane & 7);
            int cb = ks*2 + ((lane >> 3) & 1);
            uint32_t baddr = sBu + n*128 + (uint32_t)((cb ^ (n & 7)) << 4);
            uint32_t b0, b1, b2, b3;
            asm volatile("ldmatrix.sync.aligned.m8n8.x4.shared.b16 {%0,%1,%2,%3}, [%4];"
                         : "=r"(b0), "=r"(b1), "=r"(b2), "=r"(b3) : "r"(baddr));
            asm volatile("mma.sync.aligned.m16n8k16.row.col.f32.f16.f16.f32 "
                         "{%0,%1,%2,%3}, {%4,%5,%6,%7}, {%8,%9}, {%0,%1,%2,%3};"
                         : "+f"(acc[np*2][0]), "+f"(acc[np*2][1]), "+f"(acc[np*2][2]), "+f"(acc[np*2][3])
                         : "r"(a0), "r"(a1), "r"(a2), "r"(a3), "r"(b0), "r"(b1));
            asm volatile("mma.sync.aligned.m16n8k16.row.col.f32.f16.f16.f32 "
                         "{%0,%1,%2,%3}, {%4,%5,%6,%7}, {%8,%9}, {%0,%1,%2,%3};"
                         : "+f"(acc[np*2+1][0]), "+f"(acc[np*2+1][1]), "+f"(acc[np*2+1][2]), "+f"(acc[np*2+1][3])
                         : "r"(a0), "r"(a1), "r"(a2), "r"(a3), "r"(b2), "r"(b3));
        }
    }
    int g = lane >> 2, tq = lane & 3;
    uint32_t* py = g_yh + (size_t)blc*SW_;
    #pragma unroll
    for (int nt = 0; nt < 16; nt++) {
        int w = (nh*16 + nt)*4 + tq;
        __half2 h1 = __floats2half2_rn(acc[nt][0], acc[nt][1]);
        __half2 h2 = __floats2half2_rn(acc[nt][2], acc[nt][3]);
        py[(mrow + g)*W_ + w]     = *(uint32_t*)&h1;
        py[(mrow + g + 8)*W_ + w] = *(uint32_t*)&h2;
    }
}

// ---------------- K8: fp16 mma.sync conv-GEMM, register-pipelined double-buffered B ----------------
#define CONV_SMEM (199680 + 32768)
__global__ void __launch_bounds__(512) k_conv_mma() {
    extern __shared__ __align__(16) char smc[];
    char* sB = smc + 199680;
    int tid = threadIdx.x, lane = tid & 31, warp = tid >> 5;
    int bl = blockIdx.x >> 4, s0 = (blockIdx.x & 15) * 4;

    const uint32_t* ybl = g_yh + (size_t)bl * (C_*SW_);
    for (int i = tid; i < 6*130*64; i += 512) {
        int ci = i / 780, rem = i % 780;
        int ds = rem / 130, pw = rem % 130;
        int sr = s0 + ds - 1, w = pw - 1;
        uint32_t v = 0u;
        if (((unsigned)sr < (unsigned)S_) && ((unsigned)w < (unsigned)W_))
            v = ybl[(size_t)ci*SW_ + sr*W_ + w];
        int phys = ds*33280 + pw*256 + ((((ci >> 2) ^ (pw & 7))) << 4) + (ci & 3)*4;
        *(uint32_t*)(smc + phys) = v;
    }
    const uint4* bw4 = (const uint4*)g_Bw;
    {
        uint4* dst = (uint4*)sB;
        dst[tid]       = bw4[tid];
        dst[tid + 512] = bw4[tid + 512];
    }
    __syncthreads();

    float acc[2][8][4];
    #pragma unroll
    for (int mt = 0; mt < 2; mt++)
        #pragma unroll
        for (int nt = 0; nt < 8; nt++)
            #pragma unroll
            for (int j = 0; j < 4; j++) acc[mt][nt][j] = 0.f;

    uint32_t sAu = smem_u32(smc), sBu = smem_u32(sB);
    int s_row = warp >> 2;
    int wbase = (warp & 3) * 32;

    #pragma unroll 1
    for (int t = 0; t < 9; t++) {
        uint4 p0, p1;
        if (t < 8) {
            p0 = bw4[(t + 1)*1024 + tid];
            p1 = bw4[(t + 1)*1024 + tid + 512];
        }
        uint32_t sBt = sBu + (uint32_t)((t & 1)*16384);
        int tx = t % 3, ds = s_row + t / 3;
        #pragma unroll 1
        for (int ks = 0; ks < 8; ks++) {
            uint32_t a0[2], a1[2], a2[2], a3[2];
            #pragma unroll
            for (int mt = 0; mt < 2; mt++) {
                int row = wbase + mt*16 + (lane & 15) + tx;
                int cblk = ks*2 + (lane >> 4);
                uint32_t aaddr = sAu + ds*33280 + row*256 + (uint32_t)((cblk ^ (row & 7)) << 4);
                asm volatile("ldmatrix.sync.aligned.m8n8.x4.shared.b16 {%0,%1,%2,%3}, [%4];"
                             : "=r"(a0[mt]), "=r"(a1[mt]), "=r"(a2[mt]), "=r"(a3[mt]) : "r"(aaddr));
            }
            #pragma unroll
            for (int np = 0; np < 4; np++) {
                int n = (np*2 + (lane >> 4))*8 + (lane & 7);
                int cb = ks*2 + ((lane >> 3) & 1);
                uint32_t baddr = sBt + n*256 + (uint32_t)((cb ^ (n & 7)) << 4);
                uint32_t b0, b1, b2, b3;
                asm volatile("ldmatrix.sync.aligned.m8n8.x4.shared.b16 {%0,%1,%2,%3}, [%4];"
                             : "=r"(b0), "=r"(b1), "=r"(b2), "=r"(b3) : "r"(baddr));
                #pragma unroll
                for (int mt = 0; mt < 2; mt++) {
                    asm volatile("mma.sync.aligned.m16n8k16.row.col.f32.f16.f16.f32 "
                                 "{%0,%1,%2,%3}, {%4,%5,%6,%7}, {%8,%9}, {%0,%1,%2,%3};"
                                 : "+f"(acc[mt][np*2][0]), "+f"(acc[mt][np*2][1]),
                                   "+f"(acc[mt][np*2][2]), "+f"(acc[mt][np*2][3])
                                 : "r"(a0[mt]), "r"(a1[mt]), "r"(a2[mt]), "r"(a3[mt]),
                                   "r"(b0), "r"(b1));
                    asm volatile("mma.sync.aligned.m16n8k16.row.col.f32.f16.f16.f32 "
                                 "{%0,%1,%2,%3}, {%4,%5,%6,%7}, {%8,%9}, {%0,%1,%2,%3};"
                                 : "+f"(acc[mt][np*2+1][0]), "+f"(acc[mt][np*2+1][1]),
                                   "+f"(acc[mt][np*2+1][2]), "+f"(acc[mt][np*2+1][3])
                                 : "r"(a0[mt]), "r"(a1[mt]), "r"(a2[mt]), "r"(a3[mt]),
                                   "r"(b2), "r"(b3));
                }
            }
        }
        if (t < 8) {
            uint4* dst = (uint4*)(sB + ((t + 1) & 1)*16384);
            dst[tid]       = p0;
            dst[tid + 512] = p1;
            __syncthreads();
        }
    }
    int g = lane >> 2, tq = lane & 3;
    #pragma unroll
    for (int mt = 0; mt < 2; mt++) {
        uint32_t* ob = g_fh + (size_t)bl * (32*SW_) + (s0 + s_row)*W_ + wbase + mt*16 + g;
        #pragma unroll
        for (int nt = 0; nt < 8; nt++) {
            int pi = nt*4 + tq;
            __half2 hA = __floats2half2_rn(acc[mt][nt][0], acc[mt][nt][1]);
            __half2 hB = __floats2half2_rn(acc[mt][nt][2], acc[mt][nt][3]);
            ob[(size_t)pi*SW_]     = *(uint32_t*)&hA;
            ob[(size_t)pi*SW_ + 8] = *(uint32_t*)&hB;
        }
    }
}

// ---------------- K9: LayerNorm over o-pairs (+ bias) + residual ----------------
__global__ void __launch_bounds__(512) k_ln(const float* __restrict__ x,
                     const float* __restrict__ lng,
                     const float* __restrict__ lnb, float* __restrict__ out) {
    __shared__ float sbuf1[16], sbuf2[16];
    __shared__ float s_mu0, s_r0, s_mu1, s_r1;
    int blc2 = blockIdx.x, tid = threadIdx.x;
    int bl = blc2 >> 5, op = blc2 & 31;
    int o0 = op * 2;
    const uint32_t* fp = g_fh + (size_t)blc2 * SW_;
    const float* bp0 = g_bias + (size_t)o0 * SW_;
    const float* bp1 = g_bias + (size_t)(o0 + 1) * SW_;
    float v0[16], v1[16];
    float sum0 = 0.f, sq0 = 0.f, sum1 = 0.f, sq1 = 0.f;
    #pragma unroll
    for (int k = 0; k < 16; k++) {
        int i = tid + 512*k;
        uint32_t u = fp[i];
        __half2 h = *(__half2*)&u;
        float2 f = __half22float2(h);
        float t0 = f.x + bp0[i];
        float t1 = f.y + bp1[i];
        v0[k] = t0; v1[k] = t1;
        sum0 += t0; sq0 += t0*t0;
        sum1 += t1; sq1 += t1*t1;
    }
    float ts0 = blockReduceSum(sum0, sbuf1);
    __syncthreads();
    float tq0 = blockReduceSum(sq0, sbuf2);
    __syncthreads();
    float ts1 = blockReduceSum(sum1, sbuf1);
    __syncthreads();
    float tq1 = blockReduceSum(sq1, sbuf2);
    if (tid == 0) {
        float mu0 = ts0 * (1.f / (float)SW_);
        float var0 = tq0 * (1.f / (float)SW_) - mu0*mu0;
        s_mu0 = mu0; s_r0 = rsqrtf(var0 + 1e-5f);
        float mu1 = ts1 * (1.f / (float)SW_);
        float var1 = tq1 * (1.f / (float)SW_) - mu1*mu1;
        s_mu1 = mu1; s_r1 = rsqrtf(var1 + 1e-5f);
    }
    __syncthreads();
    float mu0 = s_mu0, r0 = s_r0, mu1 = s_mu1, r1 = s_r1;
    const float* xp0 = x + ((size_t)bl*C_ + o0)*SW_;
    const float* xp1 = xp0 + SW_;
    float* op0 = out + ((size_t)bl*C_ + o0)*SW_;
    float* op1 = op0 + SW_;
    #pragma unroll
    for (int k = 0; k < 16; k++) {
        int i = tid + 512*k;
        float gg = lng[i], bb = lnb[i];
        op0[i] = (v0[k] - mu0) * r0 * gg + bb + xp0[i];
        op1[i] = (v1[k] - mu1) * r1 * gg + bb + xp1[i];
    }
}

// ---------------- launch ----------------
extern "C" void kernel_launch(void* const* d_in, const int* in_sizes, int n_in,
                              void* d_out, int out_size) {
    const float* x         = (const float*)d_in[0];
    const float* nu_log    = (const float*)d_in[1];
    const float* theta_log = (const float*)d_in[2];
    const float* disp_nu   = (const float*)d_in[3];
    const float* disp_th   = (const float*)d_in[4];
    const float* mlp_w1    = (const float*)d_in[5];
    const float* mlp_b1    = (const float*)d_in[6];
    const float* mlp_w2    = (const float*)d_in[7];
    const float* mlp_b2    = (const float*)d_in[8];
    const float* fscale    = (const float*)d_in[9];
    const float* U_row_r   = (const float*)d_in[10];
    const float* U_row_i   = (const float*)d_in[11];
    const float* V_col_r   = (const float*)d_in[12];
    const float* V_col_i   = (const float*)d_in[13];
    const float* proj_W_r  = (const float*)d_in[14];
    const float* proj_W_i  = (const float*)d_in[15];
    const float* proj_b_r  = (const float*)d_in[16];
    const float* proj_b_i  = (const float*)d_in[17];
    const float* convr_k   = (const float*)d_in[18];
    const float* convr_b   = (const float*)d_in[19];
    const float* convi_k   = (const float*)d_in[20];
    const float* convi_b   = (const float*)d_in[21];
    const float* fuse_k    = (const float*)d_in[22];
    const float* fuse_b    = (const float*)d_in[23];
    const float* ln_g      = (const float*)d_in[24];
    const float* ln_b      = (const float*)d_in[25];
    float* out = (float*)d_out;

    cudaFuncSetAttribute(k_u_prep,   cudaFuncAttributeMaxDynamicSharedMemorySize, SMEM_U_BYTES);
    cudaFuncSetAttribute(k_conv_mma, cudaFuncAttributeMaxDynamicSharedMemorySize, CONV_SMEM);

    k_u_prep<<<2112, 256, SMEM_U_BYTES>>>(x, U_row_r, U_row_i, V_col_r, V_col_i,
                                          fuse_k, convr_k, convi_k, convr_b, convi_b, fuse_b,
                                          proj_W_r, proj_W_i, proj_b_r, proj_b_i);
    k_scan<<<16, 256>>>(nu_log, theta_log, disp_nu, disp_th,
                        mlp_w1, mlp_b1, mlp_w2, mlp_b2, fscale);
    k_recon_mma<<<PLANES_, 256>>>(U_row_r, U_row_i, V_col_r, V_col_i);
    k_conv_mma<<<512, 512, CONV_SMEM>>>();
    k_ln<<<1024, 512>>>(x, ln_g, ln_b, out);
}